// round 8
// baseline (speedup 1.0000x reference)
#include <cuda_runtime.h>
#include <cuda_fp16.h>
#include <math.h>
#include <stdint.h>

#define S_   256
#define B_   512
#define H_   512
#define E_   256
#define L_   4
#define OUT_ 128

// ---------------- scratch (no allocs allowed) ----------------
__device__ float g_Wh[B_ * H_];
__device__ float g_rnn[B_ * (H_ + E_)];
__device__ float g_energy[S_ * B_];

// ---------------- helpers ----------------
__device__ __forceinline__ uint32_t smem_u32(const void* p) {
    uint32_t a;
    asm("{ .reg .u64 t; cvta.to.shared.u64 t, %1; cvt.u32.u64 %0, t; }" : "=r"(a) : "l"(p));
    return a;
}

__device__ __forceinline__ void ldsm4(uint32_t* r, uint32_t addr) {
    asm volatile("ldmatrix.sync.aligned.m8n8.x4.shared.b16 {%0,%1,%2,%3}, [%4];"
                 : "=r"(r[0]), "=r"(r[1]), "=r"(r[2]), "=r"(r[3]) : "r"(addr));
}

__device__ __forceinline__ void mma16816(float* c, const uint32_t* a, uint32_t b0, uint32_t b1) {
    asm volatile(
        "mma.sync.aligned.m16n8k16.row.col.f32.f16.f16.f32 "
        "{%0,%1,%2,%3}, {%4,%5,%6,%7}, {%8,%9}, {%0,%1,%2,%3};\n"
        : "+f"(c[0]), "+f"(c[1]), "+f"(c[2]), "+f"(c[3])
        : "r"(a[0]), "r"(a[1]), "r"(a[2]), "r"(a[3]), "r"(b0), "r"(b1));
}

__device__ __forceinline__ uint2 cvt2(float4 v) {
    __half2 a = __float22half2_rn(make_float2(v.x, v.y));
    __half2 b = __float22half2_rn(make_float2(v.z, v.w));
    uint2 r;
    r.x = *reinterpret_cast<uint32_t*>(&a);
    r.y = *reinterpret_cast<uint32_t*>(&b);
    return r;
}

__device__ __forceinline__ void sts16(__half* dst, float4 v) {
    __half2* d = (__half2*)dst;
    d[0] = __float22half2_rn(make_float2(v.x, v.y));
    d[1] = __float22half2_rn(make_float2(v.z, v.w));
}

__device__ __forceinline__ float sigf(float x) { return 1.f / (1.f + __expf(-x)); }

// ============================================================
// Energy kernel: one 512-thread CTA split into two independent
// 256-thread halves (named barriers). Each half: 128 rows x 256
// cols (2 x nc of 128), warp tile 64x32, double-buffered smem.
// ============================================================
#define EBUF  3072                      // halves per buffer (128 rows * 24)
#define EHALF (4 * EBUF)                // per half: 2 A bufs + 2 W bufs
#define ESMEM_DYN (1024 + 2 * EHALF * 2)  // esum pad + tiles (bytes)

__global__ void __launch_bounds__(512, 1) energy_hmma_kernel(
    const float* __restrict__ Es, const float* __restrict__ Uw,
    const float* __restrict__ Ub, const float* __restrict__ Wh,
    const float* __restrict__ aw, const float* __restrict__ ab,
    float* __restrict__ energy) {
    extern __shared__ __align__(16) char dsm[];
    float* esum = (float*)dsm;                 // 128 floats
    __half* tiles = (__half*)(dsm + 1024);

    const int tid = threadIdx.x;
    const int half = tid >> 8;
    const int htid = tid & 255;
    const int lane = tid & 31;
    const int hwid = htid >> 5;
    const int wm = hwid >> 2, wn = hwid & 3;   // 2m x 4n warp grid per half
    const int g = lane >> 2, tg = lane & 3;
    const int lr = (lane & 7) + ((lane >> 3) & 1) * 8;
    const int lb = ((lane >> 4) & 1) * 16;
    const int r0 = blockIdx.x * 128;
    const int b0 = r0 & (B_ - 1);
    const int barid = half + 1;

    __half* sA = tiles + half * EHALF;
    __half* sW = sA + 2 * EBUF;
    const uint32_t aB = smem_u32(sA);
    const uint32_t wB = smem_u32(sW);

    const int fr = htid >> 2, fc = (htid & 3) * 4;  // fill: row = i*64+fr, col fc

    if (tid < 128) esum[tid] = 0.f;
    __syncthreads();

    for (int nc = 0; nc < 2; nc++) {
        const int cb = half * 256 + nc * 128;
        const float* Abase = Es + (size_t)r0 * H_;
        const float* Wbase = Uw + (size_t)cb * H_;
        float acc[4][4][4] = {};
        uint2 stA[2], stW[2];
#pragma unroll
        for (int i = 0; i < 2; i++) {
            const int row = i * 64 + fr;
            stA[i] = cvt2(*(const float4*)&Abase[(size_t)row * H_ + fc]);
            stW[i] = cvt2(*(const float4*)&Wbase[(size_t)row * H_ + fc]);
        }
#pragma unroll
        for (int i = 0; i < 2; i++) {
            const int row = i * 64 + fr;
            *(uint2*)(sA + row * 24 + fc) = stA[i];
            *(uint2*)(sW + row * 24 + fc) = stW[i];
        }
        asm volatile("bar.sync %0, 256;" :: "r"(barid) : "memory");

        for (int kt = 0; kt < 32; kt++) {
            const int p = kt & 1;
            if (kt + 1 < 32) {
#pragma unroll
                for (int i = 0; i < 2; i++) {
                    const int row = i * 64 + fr;
                    stA[i] = cvt2(*(const float4*)&Abase[(size_t)row * H_ + (kt + 1) * 16 + fc]);
                    stW[i] = cvt2(*(const float4*)&Wbase[(size_t)row * H_ + (kt + 1) * 16 + fc]);
                }
            }
            const uint32_t aOff = aB + (uint32_t)p * EBUF * 2;
            const uint32_t wOff = wB + (uint32_t)p * EBUF * 2;
            uint32_t af[4][4], bt[2][4];
#pragma unroll
            for (int mi = 0; mi < 4; mi++)
                ldsm4(af[mi], aOff + (uint32_t)(wm * 64 + mi * 16 + lr) * 48 + lb);
#pragma unroll
            for (int nt = 0; nt < 2; nt++)
                ldsm4(bt[nt], wOff + (uint32_t)(wn * 32 + nt * 16 + lr) * 48 + lb);
#pragma unroll
            for (int mi = 0; mi < 4; mi++)
#pragma unroll
                for (int ni = 0; ni < 4; ni++) {
                    const int nt = ni >> 1, sub = ni & 1;
                    mma16816(acc[mi][ni], af[mi], bt[nt][sub ? 1 : 0], bt[nt][sub ? 3 : 2]);
                }
            if (kt + 1 < 32) {
                __half* dA = sA + (p ^ 1) * EBUF;
                __half* dW = sW + (p ^ 1) * EBUF;
#pragma unroll
                for (int i = 0; i < 2; i++) {
                    const int row = i * 64 + fr;
                    *(uint2*)(dA + row * 24 + fc) = stA[i];
                    *(uint2*)(dW + row * 24 + fc) = stW[i];
                }
            }
            asm volatile("bar.sync %0, 256;" :: "r"(barid) : "memory");
        }

        // epilogue for this 128-col chunk
#pragma unroll
        for (int mi = 0; mi < 4; mi++)
#pragma unroll
            for (int hf = 0; hf < 2; hf++) {
                const int rl = wm * 64 + mi * 16 + g + hf * 8;
                const float* WhR = Wh + (size_t)(b0 + rl) * H_;
                float s = 0.f;
#pragma unroll
                for (int ni = 0; ni < 4; ni++) {
                    const int col = cb + wn * 32 + ni * 8 + tg * 2;
                    float v0 = acc[mi][ni][hf * 2 + 0] + Ub[col] + WhR[col];
                    float v1 = acc[mi][ni][hf * 2 + 1] + Ub[col + 1] + WhR[col + 1];
                    s += tanhf(v0) * aw[col] + tanhf(v1) * aw[col + 1];
                }
                s += __shfl_xor_sync(0xffffffffu, s, 1);
                s += __shfl_xor_sync(0xffffffffu, s, 2);
                if (tg == 0) atomicAdd(&esum[rl], s);
            }
    }
    __syncthreads();
    if (tid < 128) energy[r0 + tid] = esum[tid] + ab[0];
}

// ============================================================
// GRU fused layer: 128-thread CTAs (4 warps), tile 64 rows x 16
// h-cols, all 3 gates + both GEMMs + gate nonlinearity.
// smem rows/buf: 0-63 Ai | 64-127 Ah | 128-175 Wi | 176-223 Wh
// ============================================================
template<int KI>
__global__ void __launch_bounds__(128) gru_fused_kernel(
    const float* __restrict__ Ai, const float* __restrict__ Wi,
    const float* __restrict__ Ah, const float* __restrict__ Whh,
    const float* __restrict__ bi, const float* __restrict__ bh,
    float* __restrict__ hout) {
    __shared__ __align__(16) __half sm[2 * 224 * 24];

    const int tid = threadIdx.x;
    const int lane = tid & 31, wid = tid >> 5;   // wid = warp row-block
    const int gl = lane >> 2, tg = lane & 3;
    const int lr = (lane & 7) + ((lane >> 3) & 1) * 8;
    const int lb = ((lane >> 4) & 1) * 16;
    const int m0 = blockIdx.y * 64;
    const int nb = blockIdx.x * 16;
    const uint32_t base = smem_u32(sm);

    // fill descriptors: 7 uint2 items per thread per tile
    const float* src[7];
    uint32_t dsto[7];
    bool ish[7];
#pragma unroll
    for (int i = 0; i < 7; i++) {
        const int idx = i * 128 + tid;
        const int row = idx >> 2, c = (idx & 3) * 4;
        const float* p;
        bool h;
        if (row < 64)       { p = Ai  + (size_t)(m0 + row) * KI; h = false; }
        else if (row < 128) { p = Ah  + (size_t)(m0 + row - 64) * H_; h = true; }
        else if (row < 176) { const int q = row - 128; p = Wi  + (size_t)((q >> 4) * H_ + nb + (q & 15)) * KI; h = false; }
        else                { const int q = row - 176; p = Whh + (size_t)((q >> 4) * H_ + nb + (q & 15)) * H_; h = true; }
        src[i] = p + c;
        dsto[i] = row * 24 + c;
        ish[i] = h;
    }

    float acc_i[3][2][4] = {};
    float acc_h[3][2][4] = {};
    uint2 st[7];
#pragma unroll
    for (int i = 0; i < 7; i++) st[i] = cvt2(*(const float4*)(src[i]));
#pragma unroll
    for (int i = 0; i < 7; i++) *(uint2*)(sm + dsto[i]) = st[i];
    __syncthreads();

    constexpr int NKT = KI / 16;
    for (int kt = 0; kt < NKT; kt++) {
        const int p = kt & 1;
        const bool nxt = (kt + 1 < NKT);
        const bool nxt_h = (kt + 1 < 32);
        const bool act_h = (kt < 32);
        if (nxt) {
#pragma unroll
            for (int i = 0; i < 7; i++)
                if (!ish[i] || nxt_h) st[i] = cvt2(*(const float4*)(src[i] + (kt + 1) * 16));
        }
        const uint32_t off = base + (uint32_t)p * (224 * 48);
        uint32_t afi[4], afh[4], bwi[3][4], bwh[3][4];
        ldsm4(afi, off + (uint32_t)(wid * 16 + lr) * 48 + lb);
#pragma unroll
        for (int gt = 0; gt < 3; gt++)
            ldsm4(bwi[gt], off + (uint32_t)(128 + gt * 16 + lr) * 48 + lb);
        if (act_h) {
            ldsm4(afh, off + (uint32_t)(64 + wid * 16 + lr) * 48 + lb);
#pragma unroll
            for (int gt = 0; gt < 3; gt++)
                ldsm4(bwh[gt], off + (uint32_t)(176 + gt * 16 + lr) * 48 + lb);
        }
#pragma unroll
        for (int gt = 0; gt < 3; gt++)
#pragma unroll
            for (int sub = 0; sub < 2; sub++)
                mma16816(acc_i[gt][sub], afi, bwi[gt][sub], bwi[gt][sub + 2]);
        if (act_h) {
#pragma unroll
            for (int gt = 0; gt < 3; gt++)
#pragma unroll
                for (int sub = 0; sub < 2; sub++)
                    mma16816(acc_h[gt][sub], afh, bwh[gt][sub], bwh[gt][sub + 2]);
        }
        if (nxt) {
            __half* d = sm + (p ^ 1) * (224 * 24);
#pragma unroll
            for (int i = 0; i < 7; i++)
                if (!ish[i] || nxt_h) *(uint2*)(d + dsto[i]) = st[i];
        }
        __syncthreads();
    }

    // epilogue: gate nonlinearity, h update
#pragma unroll
    for (int hf = 0; hf < 2; hf++) {
        const int row = m0 + wid * 16 + gl + hf * 8;
#pragma unroll
        for (int sub = 0; sub < 2; sub++) {
            const int col = nb + sub * 8 + tg * 2;
            float2 hp = *(const float2*)&Ah[(size_t)row * H_ + col];
            float2 o;
#pragma unroll
            for (int j = 0; j < 2; j++) {
                const int cj = col + j;
                float ir = acc_i[0][sub][hf * 2 + j] + bi[cj];
                float hr = acc_h[0][sub][hf * 2 + j] + bh[cj];
                float iz = acc_i[1][sub][hf * 2 + j] + bi[H_ + cj];
                float hz = acc_h[1][sub][hf * 2 + j] + bh[H_ + cj];
                float in_ = acc_i[2][sub][hf * 2 + j] + bi[2 * H_ + cj];
                float hn = acc_h[2][sub][hf * 2 + j] + bh[2 * H_ + cj];
                float rr = sigf(ir + hr);
                float zz = sigf(iz + hz);
                float nn = tanhf(fmaf(rr, hn, in_));
                float hv = j ? hp.y : hp.x;
                float res = fmaf(zz, hv - nn, nn);
                if (j) o.y = res; else o.x = res;
            }
            *(float2*)&hout[(size_t)row * H_ + col] = o;
        }
    }
}

// ---------------- small GEMM: C[M,N] = A@W^T + bias, BM=64 BN=64, 256 thr ----------------
__global__ void __launch_bounds__(256, 2) sgemm64_kernel(
    const float* __restrict__ A, const float* __restrict__ W,
    const float* __restrict__ bias, float* __restrict__ C, int K, int N) {
    __shared__ __align__(16) __half sm[2 * 128 * 24];

    const int tid = threadIdx.x;
    const int lane = tid & 31, wid = tid >> 5;
    const int wm = wid >> 1, wn = wid & 1;
    const int g = lane >> 2, tg = lane & 3;
    const int lr = (lane & 7) + ((lane >> 3) & 1) * 8;
    const int lb = ((lane >> 4) & 1) * 16;
    const int m0 = blockIdx.y * 64, n0 = blockIdx.x * 64;
    const uint32_t base = smem_u32(sm);

    const int r = tid >> 2, c = (tid & 3) * 4;
    float acc[4][4] = {};
    float4 ra, rw;
    ra = *(const float4*)&A[(size_t)(m0 + r) * K + c];
    rw = *(const float4*)&W[(size_t)(n0 + r) * K + c];
    sts16(sm + r * 24 + c, ra);
    sts16(sm + (64 + r) * 24 + c, rw);
    __syncthreads();

    const int nk = K / 16;
    for (int kt = 0; kt < nk; kt++) {
        const int p = kt & 1;
        if (kt + 1 < nk) {
            ra = *(const float4*)&A[(size_t)(m0 + r) * K + (kt + 1) * 16 + c];
            rw = *(const float4*)&W[(size_t)(n0 + r) * K + (kt + 1) * 16 + c];
        }
        const uint32_t off = base + (uint32_t)p * 128 * 48;
        uint32_t af[4], bt[2][4];
        ldsm4(af, off + (uint32_t)(wm * 16 + lr) * 48 + lb);
#pragma unroll
        for (int nt = 0; nt < 2; nt++)
            ldsm4(bt[nt], off + (uint32_t)(64 + wn * 32 + nt * 16 + lr) * 48 + lb);
#pragma unroll
        for (int ni = 0; ni < 4; ni++) {
            const int nt = ni >> 1, sub = ni & 1;
            mma16816(acc[ni], af, bt[nt][sub ? 1 : 0], bt[nt][sub ? 3 : 2]);
        }
        if (kt + 1 < nk) {
            __half* d = sm + (p ^ 1) * 128 * 24;
            sts16(d + r * 24 + c, ra);
            sts16(d + (64 + r) * 24 + c, rw);
        }
        __syncthreads();
    }

#pragma unroll
    for (int hf = 0; hf < 2; hf++) {
        const int row = m0 + wm * 16 + g + hf * 8;
#pragma unroll
        for (int ni = 0; ni < 4; ni++) {
            const int col = n0 + wn * 32 + ni * 8 + tg * 2;
            float2 o;
            o.x = acc[ni][hf * 2 + 0] + bias[col];
            o.y = acc[ni][hf * 2 + 1] + bias[col + 1];
            *(float2*)&C[(size_t)row * N + col] = o;
        }
    }
}

// ---------------- fused softmax + context + embedding ----------------
__global__ void __launch_bounds__(256) attn_ctx_kernel(
    const float* __restrict__ energy, const float* __restrict__ Es,
    const int* __restrict__ x, const float* __restrict__ emb,
    float* __restrict__ rnn) {
    __shared__ float red[S_];
    __shared__ float att[S_];
    const int b = blockIdx.x;
    const int s = threadIdx.x;

    float v = energy[s * B_ + b];
    red[s] = v;
    __syncthreads();
    for (int off = S_ / 2; off; off >>= 1) {
        if (s < off) red[s] = fmaxf(red[s], red[s + off]);
        __syncthreads();
    }
    float m = red[0];
    __syncthreads();
    float ex = __expf(v - m);
    red[s] = ex;
    __syncthreads();
    for (int off = S_ / 2; off; off >>= 1) {
        if (s < off) red[s] += red[s + off];
        __syncthreads();
    }
    att[s] = ex / red[0];
    __syncthreads();

    const int h = s * 2;
    float cx = 0.f, cy = 0.f;
    const float* base = Es + (size_t)b * H_ + h;
#pragma unroll 4
    for (int s2 = 0; s2 < S_; s2++) {
        float a = att[s2];
        float2 e = *(const float2*)&base[(size_t)s2 * B_ * H_];
        cx = fmaf(a, e.x, cx);
        cy = fmaf(a, e.y, cy);
    }
    *(float2*)&rnn[(size_t)b * (H_ + E_) + h] = make_float2(cx, cy);

    rnn[(size_t)b * (H_ + E_) + H_ + s] = emb[(size_t)x[b] * E_ + s];
}

// ---------------- launch ----------------
extern "C" void kernel_launch(void* const* d_in, const int* in_sizes, int n_in,
                              void* d_out, int out_size) {
    const int*   x      = (const int*)  d_in[0];
    const float* Es     = (const float*)d_in[1];
    const float* hidden = (const float*)d_in[2];
    const float* emb    = (const float*)d_in[4];
    const float* Uw     = (const float*)d_in[5];
    const float* Ub     = (const float*)d_in[6];
    const float* Ww     = (const float*)d_in[7];
    const float* Wb     = (const float*)d_in[8];
    const float* aw     = (const float*)d_in[9];
    const float* ab     = (const float*)d_in[10];
    const float* w_ih0  = (const float*)d_in[11];
    const float* w_hh0  = (const float*)d_in[12];
    const float* b_ih0  = (const float*)d_in[13];
    const float* b_hh0  = (const float*)d_in[14];
    const float* w_ih_r = (const float*)d_in[15];
    const float* w_hh_r = (const float*)d_in[16];
    const float* b_ih_r = (const float*)d_in[17];
    const float* b_hh_r = (const float*)d_in[18];
    const float* fcw    = (const float*)d_in[19];
    const float* fcb    = (const float*)d_in[20];

    float* out     = (float*)d_out;
    float* pred    = out;               // [B, OUT]
    float* hid_out = out + B_ * OUT_;   // [L, B, H]

    float *Wh, *rnn, *energy;
    cudaGetSymbolAddress((void**)&Wh,     g_Wh);
    cudaGetSymbolAddress((void**)&rnn,    g_rnn);
    cudaGetSymbolAddress((void**)&energy, g_energy);

    cudaFuncSetAttribute(energy_hmma_kernel,
                         cudaFuncAttributeMaxDynamicSharedMemorySize, ESMEM_DYN);

    const float* hlast = hidden + (size_t)(L_ - 1) * B_ * H_;

    // 1) Wh = hidden[-1] @ Ww^T + Wb
    sgemm64_kernel<<<dim3(H_ / 64, B_ / 64), 256>>>(hlast, Ww, Wb, Wh, H_, H_);

    // 2) fused energy (split-CTA named-barrier pipelines)
    energy_hmma_kernel<<<(S_ * B_) / 128, 512, ESMEM_DYN>>>(Es, Uw, Ub, Wh, aw, ab, energy);

    // 3) softmax + context + embedding
    attn_ctx_kernel<<<B_, 256>>>(energy, Es, x, emb, rnn);

    // 4) fused GRU layers (128-thread CTAs, grid 256)
    gru_fused_kernel<768><<<dim3(H_ / 16, B_ / 64), 128>>>(
        rnn, w_ih0, hidden, w_hh0, b_ih0, b_hh0, hid_out);
    for (int l = 1; l < L_; l++) {
        gru_fused_kernel<512><<<dim3(H_ / 16, B_ / 64), 128>>>(
            hid_out + (size_t)(l - 1) * B_ * H_,
            w_ih_r + (size_t)(l - 1) * 3 * H_ * H_,
            hidden + (size_t)l * B_ * H_,
            w_hh_r + (size_t)(l - 1) * 3 * H_ * H_,
            b_ih_r + (size_t)(l - 1) * 3 * H_,
            b_hh_r + (size_t)(l - 1) * 3 * H_,
            hid_out + (size_t)l * B_ * H_);
    }

    // 5) predictions = h_last @ fcw^T + fcb
    sgemm64_kernel<<<dim3(OUT_ / 64, B_ / 64), 256>>>(
        hid_out + (size_t)(L_ - 1) * B_ * H_, fcw, fcb, pred, H_, OUT_);
}

// round 9
// speedup vs baseline: 1.1298x; 1.1298x over previous
#include <cuda_runtime.h>
#include <cuda_fp16.h>
#include <math.h>
#include <stdint.h>

#define S_   256
#define B_   512
#define H_   512
#define E_   256
#define L_   4
#define OUT_ 128

// ---------------- scratch (no allocs allowed) ----------------
__device__ float  g_Wh[B_ * H_];
__device__ float  g_energy[S_ * B_];
__device__ __half g_EsH[S_ * B_ * H_];
__device__ __half g_UwH[H_ * H_];
__device__ __half g_WiH0[3 * H_ * (H_ + E_)];
__device__ __half g_WhH0[3 * H_ * H_];
__device__ __half g_WiHr[(L_ - 1) * 3 * H_ * H_];
__device__ __half g_WhHr[(L_ - 1) * 3 * H_ * H_];
__device__ __half g_hidH[L_ * B_ * H_];
__device__ __half g_rnnH[B_ * (H_ + E_)];
__device__ __half g_houtH[L_ * B_ * H_];

// ---------------- helpers ----------------
__device__ __forceinline__ uint32_t smem_u32(const void* p) {
    uint32_t a;
    asm("{ .reg .u64 t; cvta.to.shared.u64 t, %1; cvt.u32.u64 %0, t; }" : "=r"(a) : "l"(p));
    return a;
}
__device__ __forceinline__ void ldsm4(uint32_t* r, uint32_t addr) {
    asm volatile("ldmatrix.sync.aligned.m8n8.x4.shared.b16 {%0,%1,%2,%3}, [%4];"
                 : "=r"(r[0]), "=r"(r[1]), "=r"(r[2]), "=r"(r[3]) : "r"(addr));
}
__device__ __forceinline__ void mma16816(float* c, const uint32_t* a, uint32_t b0, uint32_t b1) {
    asm volatile(
        "mma.sync.aligned.m16n8k16.row.col.f32.f16.f16.f32 "
        "{%0,%1,%2,%3}, {%4,%5,%6,%7}, {%8,%9}, {%0,%1,%2,%3};\n"
        : "+f"(c[0]), "+f"(c[1]), "+f"(c[2]), "+f"(c[3])
        : "r"(a[0]), "r"(a[1]), "r"(a[2]), "r"(a[3]), "r"(b0), "r"(b1));
}
__device__ __forceinline__ void cp16(uint32_t daddr, const void* saddr) {
    asm volatile("cp.async.cg.shared.global [%0], [%1], 16;" :: "r"(daddr), "l"(saddr) : "memory");
}
#define CP_COMMIT() asm volatile("cp.async.commit_group;" ::: "memory")
#define CP_WAIT(n)  asm volatile("cp.async.wait_group " #n ";" ::: "memory")

__device__ __forceinline__ void sts16(__half* dst, float4 v) {
    __half2* d = (__half2*)dst;
    d[0] = __float22half2_rn(make_float2(v.x, v.y));
    d[1] = __float22half2_rn(make_float2(v.z, v.w));
}
__device__ __forceinline__ float sigf(float x) { return 1.f / (1.f + __expf(-x)); }

// ---------------- fp32 -> fp16 convert (exact-size grids) ----------------
__global__ void cvt_kernel(const float* __restrict__ src, __half* __restrict__ dst) {
    const int i = blockIdx.x * 256 + threadIdx.x;   // 4 floats per thread
    float4 v = ((const float4*)src)[i];
    __half2 a = __float22half2_rn(make_float2(v.x, v.y));
    __half2 b = __float22half2_rn(make_float2(v.z, v.w));
    uint2 o;
    o.x = *reinterpret_cast<uint32_t*>(&a);
    o.y = *reinterpret_cast<uint32_t*>(&b);
    ((uint2*)dst)[i] = o;
}

// ============================================================
// Energy kernel: fp16 operands via cp.async, 4-stage pipeline.
// Block 128 rows x 512 cols (nc loop x2 of 256), 512 thr,
// 16 warps (2m x 8n), warp tile 64x32.
// ============================================================
#define EST_A 6144                 // 128 rows * 48B
#define EST   18432                // + 256 rows * 48B for W
#define ESMEM_DYN (512 + 4 * EST)  // 74240

__global__ void __launch_bounds__(512, 1) energy_async_kernel(
    const __half* __restrict__ EsH, const __half* __restrict__ UwH,
    const float* __restrict__ Ub, const float* __restrict__ Wh,
    const float* __restrict__ aw, const float* __restrict__ ab,
    float* __restrict__ energy) {
    extern __shared__ __align__(16) char dsm[];
    float* esum = (float*)dsm;
    const uint32_t tbase = smem_u32(dsm + 512);

    const int tid = threadIdx.x;
    const int lane = tid & 31, wid = tid >> 5;
    const int wm = wid >> 3, wn = wid & 7;
    const int g = lane >> 2, tg = lane & 3;
    const int lr = (lane & 7) + ((lane >> 3) & 1) * 8;
    const int lb = ((lane >> 4) & 1) * 16;
    const int r0 = blockIdx.x * 128;
    const int b0 = r0 & (B_ - 1);

    const int frow = tid >> 1, fhalf = tid & 1;   // W: row 0..255; A: tid<256 row 0..127

    if (tid < 128) esum[tid] = 0.f;
    __syncthreads();

    for (int nc = 0; nc < 2; nc++) {
        const __half* Abase = EsH + (size_t)r0 * H_;
        const __half* Wbase = UwH + (size_t)(nc * 256) * H_;
        float acc[4][4][4] = {};

        // prologue: stages 0..2
#pragma unroll
        for (int s = 0; s < 3; s++) {
            const uint32_t sb = tbase + (uint32_t)s * EST;
            if (tid < 256)
                cp16(sb + frow * 48 + fhalf * 16,
                     Abase + (size_t)frow * H_ + s * 16 + fhalf * 8);
            cp16(sb + EST_A + frow * 48 + fhalf * 16,
                 Wbase + (size_t)frow * H_ + s * 16 + fhalf * 8);
            CP_COMMIT();
        }

        for (int kt = 0; kt < 32; kt++) {
            const int s = kt & 3;
            CP_WAIT(2);
            __syncthreads();

            const uint32_t aOff = tbase + (uint32_t)s * EST;
            const uint32_t wOff = aOff + EST_A;
            uint32_t af[4][4], bt[2][4];
#pragma unroll
            for (int mi = 0; mi < 4; mi++)
                ldsm4(af[mi], aOff + (uint32_t)(wm * 64 + mi * 16 + lr) * 48 + lb);
#pragma unroll
            for (int nt = 0; nt < 2; nt++)
                ldsm4(bt[nt], wOff + (uint32_t)(wn * 32 + nt * 16 + lr) * 48 + lb);
#pragma unroll
            for (int mi = 0; mi < 4; mi++)
#pragma unroll
                for (int ni = 0; ni < 4; ni++) {
                    const int nt = ni >> 1, sub = ni & 1;
                    mma16816(acc[mi][ni], af[mi], bt[nt][sub ? 1 : 0], bt[nt][sub ? 3 : 2]);
                }
            if (kt + 3 < 32) {
                const int ns = (kt + 3) & 3;
                const uint32_t sb = tbase + (uint32_t)ns * EST;
                if (tid < 256)
                    cp16(sb + frow * 48 + fhalf * 16,
                         Abase + (size_t)frow * H_ + (kt + 3) * 16 + fhalf * 8);
                cp16(sb + EST_A + frow * 48 + fhalf * 16,
                     Wbase + (size_t)frow * H_ + (kt + 3) * 16 + fhalf * 8);
            }
            CP_COMMIT();
        }

        // epilogue for this 256-col chunk
#pragma unroll
        for (int mi = 0; mi < 4; mi++)
#pragma unroll
            for (int hf = 0; hf < 2; hf++) {
                const int rl = wm * 64 + mi * 16 + g + hf * 8;
                const float* WhR = Wh + (size_t)(b0 + rl) * H_;
                float s = 0.f;
#pragma unroll
                for (int ni = 0; ni < 4; ni++) {
                    const int col = nc * 256 + wn * 32 + ni * 8 + tg * 2;
                    float v0 = acc[mi][ni][hf * 2 + 0] + Ub[col] + WhR[col];
                    float v1 = acc[mi][ni][hf * 2 + 1] + Ub[col + 1] + WhR[col + 1];
                    s += tanhf(v0) * aw[col] + tanhf(v1) * aw[col + 1];
                }
                s += __shfl_xor_sync(0xffffffffu, s, 1);
                s += __shfl_xor_sync(0xffffffffu, s, 2);
                if (tg == 0) atomicAdd(&esum[rl], s);
            }
    }
    __syncthreads();
    if (tid < 128) energy[r0 + tid] = esum[tid] + ab[0];
}

// ============================================================
// GRU fused layer: fp16 operands via cp.async, 3-stage pipeline.
// 256 thr, tile 64 rows x 32 h-cols, warps 4m x 2n (16x16).
// smem rows/stage: 0-63 Ai | 64-127 Ah | 128-223 Wi | 224-319 Wh
// r,z accumulators merged (gi+gh summed in-MMA).
// ============================================================
#define GST 15360   // 320 rows * 48B per stage

template<int KI>
__global__ void __launch_bounds__(256, 2) gru_fused_kernel(
    const __half* __restrict__ AiH, const __half* __restrict__ WiH,
    const __half* __restrict__ AhH, const __half* __restrict__ WhH,
    const float* __restrict__ Ahf,
    const float* __restrict__ bi, const float* __restrict__ bh,
    float* __restrict__ hout, __half* __restrict__ houtH) {
    __shared__ __align__(16) char sm[3 * GST];

    const int tid = threadIdx.x;
    const int lane = tid & 31, wid = tid >> 5;
    const int wm = wid >> 1, wn = wid & 1;
    const int gl = lane >> 2, tg = lane & 3;
    const int lr = (lane & 7) + ((lane >> 3) & 1) * 8;
    const int lb = ((lane >> 4) & 1) * 16;
    const int m0 = blockIdx.y * 64;
    const int nb = blockIdx.x * 32;
    const uint32_t base = smem_u32(sm);

    // fill descriptors: 640 cp16 ops, 3 slots per thread
    const __half* srcp[3];
    uint32_t dsto[3];
    bool ish[3], valid[3];
#pragma unroll
    for (int i = 0; i < 3; i++) {
        const int idx = i * 256 + tid;
        valid[i] = idx < 640;
        const int row = (idx < 640) ? (idx >> 1) : 0;
        const int hf = idx & 1;
        const __half* p;
        bool h;
        if (row < 64)       { p = AiH + (size_t)(m0 + row) * KI; h = false; }
        else if (row < 128) { p = AhH + (size_t)(m0 + row - 64) * H_; h = true; }
        else if (row < 224) { const int q = row - 128; p = WiH + (size_t)((q >> 5) * H_ + nb + (q & 31)) * KI; h = false; }
        else                { const int q = row - 224; p = WhH + (size_t)((q >> 5) * H_ + nb + (q & 31)) * H_; h = true; }
        srcp[i] = p + hf * 8;
        dsto[i] = row * 48 + hf * 16;
        ish[i] = h;
    }

    float acc_rz[2][2][4] = {};
    float acc_n0[2][4] = {};
    float acc_n1[2][4] = {};

    constexpr int NKT = KI / 16;
    // prologue stages 0,1
#pragma unroll
    for (int s = 0; s < 2; s++) {
#pragma unroll
        for (int i = 0; i < 3; i++)
            if (valid[i] && (!ish[i] || s < 32))
                cp16(base + s * GST + dsto[i], srcp[i] + s * 16);
        CP_COMMIT();
    }

    for (int kt = 0; kt < NKT; kt++) {
        const int s = kt % 3;
        CP_WAIT(1);
        __syncthreads();

        const uint32_t off = base + (uint32_t)s * GST;
        const bool act_h = (kt < 32);
        uint32_t afi[4], afh[4], bwi[3][4], bwh[3][4];
        ldsm4(afi, off + (uint32_t)(wm * 16 + lr) * 48 + lb);
#pragma unroll
        for (int gt = 0; gt < 3; gt++)
            ldsm4(bwi[gt], off + (uint32_t)(128 + gt * 32 + wn * 16 + lr) * 48 + lb);
        if (act_h) {
            ldsm4(afh, off + (uint32_t)(64 + wm * 16 + lr) * 48 + lb);
#pragma unroll
            for (int gt = 0; gt < 3; gt++)
                ldsm4(bwh[gt], off + (uint32_t)(224 + gt * 32 + wn * 16 + lr) * 48 + lb);
        }
#pragma unroll
        for (int sub = 0; sub < 2; sub++) {
            mma16816(acc_rz[0][sub], afi, bwi[0][sub], bwi[0][sub + 2]);
            mma16816(acc_rz[1][sub], afi, bwi[1][sub], bwi[1][sub + 2]);
            mma16816(acc_n0[sub],    afi, bwi[2][sub], bwi[2][sub + 2]);
        }
        if (act_h) {
#pragma unroll
            for (int sub = 0; sub < 2; sub++) {
                mma16816(acc_rz[0][sub], afh, bwh[0][sub], bwh[0][sub + 2]);
                mma16816(acc_rz[1][sub], afh, bwh[1][sub], bwh[1][sub + 2]);
                mma16816(acc_n1[sub],    afh, bwh[2][sub], bwh[2][sub + 2]);
            }
        }
        if (kt + 2 < NKT) {
            const int ns = (kt + 2) % 3;
#pragma unroll
            for (int i = 0; i < 3; i++)
                if (valid[i] && (!ish[i] || (kt + 2) < 32))
                    cp16(base + ns * GST + dsto[i], srcp[i] + (kt + 2) * 16);
        }
        CP_COMMIT();
    }

    // epilogue: gate nonlinearity, h update (fp32 h from Ahf)
#pragma unroll
    for (int hf = 0; hf < 2; hf++) {
        const int row = m0 + wm * 16 + gl + hf * 8;
#pragma unroll
        for (int sub = 0; sub < 2; sub++) {
            const int col = nb + wn * 16 + sub * 8 + tg * 2;
            float2 hp = *(const float2*)&Ahf[(size_t)row * H_ + col];
            float2 o;
#pragma unroll
            for (int j = 0; j < 2; j++) {
                const int cj = col + j;
                float rr = sigf(acc_rz[0][sub][hf * 2 + j] + bi[cj] + bh[cj]);
                float zz = sigf(acc_rz[1][sub][hf * 2 + j] + bi[H_ + cj] + bh[H_ + cj]);
                float nn = tanhf(acc_n0[sub][hf * 2 + j] + bi[2 * H_ + cj] +
                                 rr * (acc_n1[sub][hf * 2 + j] + bh[2 * H_ + cj]));
                float hv = j ? hp.y : hp.x;
                float res = fmaf(zz, hv - nn, nn);
                if (j) o.y = res; else o.x = res;
            }
            *(float2*)&hout[(size_t)row * H_ + col] = o;
            *(__half2*)&houtH[(size_t)row * H_ + col] = __float22half2_rn(o);
        }
    }
}

// ---------------- small GEMM: C[M,N] = A@W^T + bias (fp32 in, 64x64) ----------------
__global__ void __launch_bounds__(256, 2) sgemm64_kernel(
    const float* __restrict__ A, const float* __restrict__ W,
    const float* __restrict__ bias, float* __restrict__ C, int K, int N) {
    __shared__ __align__(16) __half sm[2 * 128 * 24];

    const int tid = threadIdx.x;
    const int lane = tid & 31, wid = tid >> 5;
    const int wm = wid >> 1, wn = wid & 1;
    const int g = lane >> 2, tg = lane & 3;
    const int lr = (lane & 7) + ((lane >> 3) & 1) * 8;
    const int lb = ((lane >> 4) & 1) * 16;
    const int m0 = blockIdx.y * 64, n0 = blockIdx.x * 64;
    const uint32_t base = smem_u32(sm);

    const int r = tid >> 2, c = (tid & 3) * 4;
    float acc[4][4] = {};
    float4 ra, rw;
    ra = *(const float4*)&A[(size_t)(m0 + r) * K + c];
    rw = *(const float4*)&W[(size_t)(n0 + r) * K + c];
    sts16(sm + r * 24 + c, ra);
    sts16(sm + (64 + r) * 24 + c, rw);
    __syncthreads();

    const int nk = K / 16;
    for (int kt = 0; kt < nk; kt++) {
        const int p = kt & 1;
        if (kt + 1 < nk) {
            ra = *(const float4*)&A[(size_t)(m0 + r) * K + (kt + 1) * 16 + c];
            rw = *(const float4*)&W[(size_t)(n0 + r) * K + (kt + 1) * 16 + c];
        }
        const uint32_t off = base + (uint32_t)p * 128 * 48;
        uint32_t af[4], bt[2][4];
        ldsm4(af, off + (uint32_t)(wm * 16 + lr) * 48 + lb);
#pragma unroll
        for (int nt = 0; nt < 2; nt++)
            ldsm4(bt[nt], off + (uint32_t)(64 + wn * 32 + nt * 16 + lr) * 48 + lb);
#pragma unroll
        for (int ni = 0; ni < 4; ni++) {
            const int nt = ni >> 1, sub = ni & 1;
            mma16816(acc[ni], af, bt[nt][sub ? 1 : 0], bt[nt][sub ? 3 : 2]);
        }
        if (kt + 1 < nk) {
            __half* d = sm + (p ^ 1) * 128 * 24;
            sts16(d + r * 24 + c, ra);
            sts16(d + (64 + r) * 24 + c, rw);
        }
        __syncthreads();
    }

#pragma unroll
    for (int hf = 0; hf < 2; hf++) {
        const int row = m0 + wm * 16 + g + hf * 8;
#pragma unroll
        for (int ni = 0; ni < 4; ni++) {
            const int col = n0 + wn * 32 + ni * 8 + tg * 2;
            float2 o;
            o.x = acc[ni][hf * 2 + 0] + bias[col];
            o.y = acc[ni][hf * 2 + 1] + bias[col + 1];
            *(float2*)&C[(size_t)row * N + col] = o;
        }
    }
}

// ---------------- fused softmax + context + embedding (fp16 rnn out) ----------------
__global__ void __launch_bounds__(256) attn_ctx_kernel(
    const float* __restrict__ energy, const float* __restrict__ Es,
    const int* __restrict__ x, const float* __restrict__ emb,
    __half* __restrict__ rnnH) {
    __shared__ float red[S_];
    __shared__ float att[S_];
    const int b = blockIdx.x;
    const int s = threadIdx.x;

    float v = energy[s * B_ + b];
    red[s] = v;
    __syncthreads();
    for (int off = S_ / 2; off; off >>= 1) {
        if (s < off) red[s] = fmaxf(red[s], red[s + off]);
        __syncthreads();
    }
    float m = red[0];
    __syncthreads();
    float ex = __expf(v - m);
    red[s] = ex;
    __syncthreads();
    for (int off = S_ / 2; off; off >>= 1) {
        if (s < off) red[s] += red[s + off];
        __syncthreads();
    }
    att[s] = ex / red[0];
    __syncthreads();

    const int h = s * 2;
    float cx = 0.f, cy = 0.f;
    const float* base = Es + (size_t)b * H_ + h;
#pragma unroll 4
    for (int s2 = 0; s2 < S_; s2++) {
        float a = att[s2];
        float2 e = *(const float2*)&base[(size_t)s2 * B_ * H_];
        cx = fmaf(a, e.x, cx);
        cy = fmaf(a, e.y, cy);
    }
    *(__half2*)&rnnH[(size_t)b * (H_ + E_) + h] = __float22half2_rn(make_float2(cx, cy));
    rnnH[(size_t)b * (H_ + E_) + H_ + s] = __float2half(emb[(size_t)x[b] * E_ + s]);
}

// ---------------- launch ----------------
extern "C" void kernel_launch(void* const* d_in, const int* in_sizes, int n_in,
                              void* d_out, int out_size) {
    const int*   x      = (const int*)  d_in[0];
    const float* Es     = (const float*)d_in[1];
    const float* hidden = (const float*)d_in[2];
    const float* emb    = (const float*)d_in[4];
    const float* Uw     = (const float*)d_in[5];
    const float* Ub     = (const float*)d_in[6];
    const float* Ww     = (const float*)d_in[7];
    const float* Wb     = (const float*)d_in[8];
    const float* aw     = (const float*)d_in[9];
    const float* ab     = (const float*)d_in[10];
    const float* w_ih0  = (const float*)d_in[11];
    const float* w_hh0  = (const float*)d_in[12];
    const float* b_ih0  = (const float*)d_in[13];
    const float* b_hh0  = (const float*)d_in[14];
    const float* w_ih_r = (const float*)d_in[15];
    const float* w_hh_r = (const float*)d_in[16];
    const float* b_ih_r = (const float*)d_in[17];
    const float* b_hh_r = (const float*)d_in[18];
    const float* fcw    = (const float*)d_in[19];
    const float* fcb    = (const float*)d_in[20];

    float* out     = (float*)d_out;
    float* pred    = out;               // [B, OUT]
    float* hid_out = out + B_ * OUT_;   // [L, B, H]

    float *Wh, *energy;
    __half *EsH, *UwH, *WiH0, *WhH0, *WiHr, *WhHr, *hidH, *rnnH, *houtH;
    cudaGetSymbolAddress((void**)&Wh,     g_Wh);
    cudaGetSymbolAddress((void**)&energy, g_energy);
    cudaGetSymbolAddress((void**)&EsH,    g_EsH);
    cudaGetSymbolAddress((void**)&UwH,    g_UwH);
    cudaGetSymbolAddress((void**)&WiH0,   g_WiH0);
    cudaGetSymbolAddress((void**)&WhH0,   g_WhH0);
    cudaGetSymbolAddress((void**)&WiHr,   g_WiHr);
    cudaGetSymbolAddress((void**)&WhHr,   g_WhHr);
    cudaGetSymbolAddress((void**)&hidH,   g_hidH);
    cudaGetSymbolAddress((void**)&rnnH,   g_rnnH);
    cudaGetSymbolAddress((void**)&houtH,  g_houtH);

    cudaFuncSetAttribute(energy_async_kernel,
                         cudaFuncAttributeMaxDynamicSharedMemorySize, ESMEM_DYN);

    const float* hlast = hidden + (size_t)(L_ - 1) * B_ * H_;

    // 0) fp32 -> fp16 conversions
    cvt_kernel<<<S_ * B_ * H_ / 1024, 256>>>(Es, EsH);
    cvt_kernel<<<H_ * H_ / 1024, 256>>>(Uw, UwH);
    cvt_kernel<<<3 * H_ * (H_ + E_) / 1024, 256>>>(w_ih0, WiH0);
    cvt_kernel<<<3 * H_ * H_ / 1024, 256>>>(w_hh0, WhH0);
    cvt_kernel<<<(L_ - 1) * 3 * H_ * H_ / 1024, 256>>>(w_ih_r, WiHr);
    cvt_kernel<<<(L_ - 1) * 3 * H_ * H_ / 1024, 256>>>(w_hh_r, WhHr);
    cvt_kernel<<<L_ * B_ * H_ / 1024, 256>>>(hidden, hidH);

    // 1) Wh = hidden[-1] @ Ww^T + Wb
    sgemm64_kernel<<<dim3(H_ / 64, B_ / 64), 256>>>(hlast, Ww, Wb, Wh, H_, H_);

    // 2) fused energy (cp.async 4-stage)
    energy_async_kernel<<<(S_ * B_) / 128, 512, ESMEM_DYN>>>(
        EsH, UwH, Ub, Wh, aw, ab, energy);

    // 3) softmax + context + embedding -> fp16 rnn
    attn_ctx_kernel<<<B_, 256>>>(energy, Es, x, emb, rnnH);

    // 4) fused GRU layers (cp.async 3-stage, merged r/z acc)
    gru_fused_kernel<768><<<dim3(H_ / 32, B_ / 64), 256>>>(
        rnnH, WiH0, hidH, WhH0, hidden, b_ih0, b_hh0, hid_out, houtH);
    for (int l = 1; l < L_; l++) {
        gru_fused_kernel<512><<<dim3(H_ / 32, B_ / 64), 256>>>(
            houtH + (size_t)(l - 1) * B_ * H_,
            WiHr + (size_t)(l - 1) * 3 * H_ * H_,
            hidH + (size_t)l * B_ * H_,
            WhHr + (size_t)(l - 1) * 3 * H_ * H_,
            hidden + (size_t)l * B_ * H_,
            b_ih_r + (size_t)(l - 1) * 3 * H_,
            b_hh_r + (size_t)(l - 1) * 3 * H_,
            hid_out + (size_t)l * B_ * H_,
            houtH + (size_t)l * B_ * H_);
    }

    // 5) predictions = h_last @ fcw^T + fcb
    sgemm64_kernel<<<dim3(OUT_ / 64, B_ / 64), 256>>>(
        hid_out + (size_t)(L_ - 1) * B_ * H_, fcw, fcb, pred, H_, OUT_);
}

// round 10
// speedup vs baseline: 1.1511x; 1.0188x over previous
#include <cuda_runtime.h>
#include <cuda_fp16.h>
#include <math.h>
#include <stdint.h>

#define S_   256
#define B_   512
#define H_   512
#define E_   256
#define L_   4
#define OUT_ 128

// ---------------- scratch (no allocs allowed) ----------------
__device__ float  g_Wh[B_ * H_];
__device__ float  g_energy[S_ * B_];
__device__ __half g_UwH[H_ * H_];
__device__ __half g_WiH0[3 * H_ * (H_ + E_)];
__device__ __half g_WhH0[3 * H_ * H_];
__device__ __half g_WiHr[(L_ - 1) * 3 * H_ * H_];
__device__ __half g_WhHr[(L_ - 1) * 3 * H_ * H_];
__device__ __half g_hidH[L_ * B_ * H_];
__device__ __half g_rnnH[B_ * (H_ + E_)];
__device__ __half g_houtH[L_ * B_ * H_];

// ---------------- helpers ----------------
__device__ __forceinline__ uint32_t smem_u32(const void* p) {
    uint32_t a;
    asm("{ .reg .u64 t; cvta.to.shared.u64 t, %1; cvt.u32.u64 %0, t; }" : "=r"(a) : "l"(p));
    return a;
}
__device__ __forceinline__ void ldsm4(uint32_t* r, uint32_t addr) {
    asm volatile("ldmatrix.sync.aligned.m8n8.x4.shared.b16 {%0,%1,%2,%3}, [%4];"
                 : "=r"(r[0]), "=r"(r[1]), "=r"(r[2]), "=r"(r[3]) : "r"(addr));
}
__device__ __forceinline__ void mma16816(float* c, const uint32_t* a, uint32_t b0, uint32_t b1) {
    asm volatile(
        "mma.sync.aligned.m16n8k16.row.col.f32.f16.f16.f32 "
        "{%0,%1,%2,%3}, {%4,%5,%6,%7}, {%8,%9}, {%0,%1,%2,%3};\n"
        : "+f"(c[0]), "+f"(c[1]), "+f"(c[2]), "+f"(c[3])
        : "r"(a[0]), "r"(a[1]), "r"(a[2]), "r"(a[3]), "r"(b0), "r"(b1));
}
__device__ __forceinline__ void cp16(uint32_t daddr, const void* saddr) {
    asm volatile("cp.async.cg.shared.global [%0], [%1], 16;" :: "r"(daddr), "l"(saddr) : "memory");
}
#define CP_COMMIT() asm volatile("cp.async.commit_group;" ::: "memory")
#define CP_WAIT(n)  asm volatile("cp.async.wait_group " #n ";" ::: "memory")

__device__ __forceinline__ void sts16(__half* dst, float4 v) {
    __half2* d = (__half2*)dst;
    d[0] = __float22half2_rn(make_float2(v.x, v.y));
    d[1] = __float22half2_rn(make_float2(v.z, v.w));
}
__device__ __forceinline__ uint32_t packh2(float a, float b) {
    __half2 h = __float22half2_rn(make_float2(a, b));
    return *reinterpret_cast<uint32_t*>(&h);
}
__device__ __forceinline__ float sigf(float x) { return 1.f / (1.f + __expf(-x)); }

// ---------------- merged fp32 -> fp16 conversions (one launch) ----------------
// quad index space (1 quad = 4 floats), compile-time segment boundaries.
#define Q_UW   (H_ * H_ / 4)                               // 65536
#define Q_WI0  (Q_UW + 3 * H_ * (H_ + E_) / 4)             // 360448
#define Q_WH0  (Q_WI0 + 3 * H_ * H_ / 4)                   // 557056
#define Q_WIR  (Q_WH0 + (L_ - 1) * 3 * H_ * H_ / 4)        // 1146880
#define Q_WHR  (Q_WIR + (L_ - 1) * 3 * H_ * H_ / 4)        // 1736704
#define Q_HID  (Q_WHR + L_ * B_ * H_ / 4)                  // 1998848
#define CVT_BLOCKS (Q_HID / 256)                           // 7808

__global__ void cvt_all_kernel(
    const float* __restrict__ Uw,   __half* __restrict__ UwH,
    const float* __restrict__ wi0,  __half* __restrict__ WiH0,
    const float* __restrict__ wh0,  __half* __restrict__ WhH0,
    const float* __restrict__ wir,  __half* __restrict__ WiHr,
    const float* __restrict__ whr,  __half* __restrict__ WhHr,
    const float* __restrict__ hid,  __half* __restrict__ hidH) {
    const int i = blockIdx.x * 256 + threadIdx.x;
    const float* src;
    __half* dst;
    int off;
    if (i < Q_UW)       { src = Uw;  dst = UwH;  off = 0; }
    else if (i < Q_WI0) { src = wi0; dst = WiH0; off = Q_UW; }
    else if (i < Q_WH0) { src = wh0; dst = WhH0; off = Q_WI0; }
    else if (i < Q_WIR) { src = wir; dst = WiHr; off = Q_WH0; }
    else if (i < Q_WHR) { src = whr; dst = WhHr; off = Q_WIR; }
    else                { src = hid; dst = hidH; off = Q_WHR; }
    const int j = i - off;
    float4 v = ((const float4*)src)[j];
    uint2 o;
    o.x = packh2(v.x, v.y);
    o.y = packh2(v.z, v.w);
    ((uint2*)dst)[j] = o;
}

// ============================================================
// Energy kernel: A = Es fp32 via cp.async (no pre-convert),
// manual A-fragment LDS+cvt; B = UwH fp16 via cp.async + ldsm.
// Block 128 rows x 512 cols (nc x2 of 256), 512 thr, 16 warps
// (2m x 8n), warp tile 64x32, 4-stage pipeline.
// ============================================================
#define EAS 12288                         // A stage: 128 rows * 96B (24 floats)
#define EWS 12288                         // W stage: 256 rows * 48B
#define ESMEM_DYN (512 + 4 * EAS + 4 * EWS)   // 98816

__global__ void __launch_bounds__(512, 1) energy_async_kernel(
    const float* __restrict__ Es, const __half* __restrict__ UwH,
    const float* __restrict__ Ub, const float* __restrict__ Wh,
    const float* __restrict__ aw, const float* __restrict__ ab,
    float* __restrict__ energy) {
    extern __shared__ __align__(16) char dsm[];
    float* esum = (float*)dsm;
    char* aRegion = dsm + 512;
    char* wRegion = dsm + 512 + 4 * EAS;
    const uint32_t aBase = smem_u32(aRegion);
    const uint32_t wBase = smem_u32(wRegion);

    const int tid = threadIdx.x;
    const int lane = tid & 31, wid = tid >> 5;
    const int wm = wid >> 3, wn = wid & 7;
    const int g = lane >> 2, tg = lane & 3;
    const int lr = (lane & 7) + ((lane >> 3) & 1) * 8;
    const int lb = ((lane >> 4) & 1) * 16;
    const int r0 = blockIdx.x * 128;
    const int b0 = r0 & (B_ - 1);

    const int rowA = tid >> 2, quad = tid & 3;   // A fill: 512 cp16 = 128 rows x 4 quads
    const int rowW = tid >> 1, wh = tid & 1;     // W fill: 512 cp16 = 256 rows x 2 halves

    if (tid < 128) esum[tid] = 0.f;
    __syncthreads();

    for (int nc = 0; nc < 2; nc++) {
        const float* Abase = Es + (size_t)r0 * H_;
        const __half* Wb2 = UwH + (size_t)(nc * 256) * H_;
        float acc[4][4][4] = {};

        // prologue: stages 0..2
#pragma unroll
        for (int s = 0; s < 3; s++) {
            cp16(aBase + s * EAS + rowA * 96 + quad * 16,
                 Abase + (size_t)rowA * H_ + s * 16 + quad * 4);
            cp16(wBase + s * EWS + rowW * 48 + wh * 16,
                 Wb2 + (size_t)rowW * H_ + s * 16 + wh * 8);
            CP_COMMIT();
        }

        for (int kt = 0; kt < 32; kt++) {
            const int s = kt & 3;
            CP_WAIT(2);
            __syncthreads();

            const float* sA = (const float*)(aRegion + s * EAS);
            const uint32_t wOff = wBase + (uint32_t)s * EWS;

            // A fragments: manual LDS.64 + f16x2 pack (matches ldsm layout)
            uint32_t af[4][4];
#pragma unroll
            for (int mi = 0; mi < 4; mi++) {
                const int rb = wm * 64 + mi * 16 + g;
                float2 f0 = *(const float2*)&sA[rb * 24 + tg * 2];
                float2 f1 = *(const float2*)&sA[(rb + 8) * 24 + tg * 2];
                float2 f2 = *(const float2*)&sA[rb * 24 + tg * 2 + 8];
                float2 f3 = *(const float2*)&sA[(rb + 8) * 24 + tg * 2 + 8];
                af[mi][0] = packh2(f0.x, f0.y);
                af[mi][1] = packh2(f1.x, f1.y);
                af[mi][2] = packh2(f2.x, f2.y);
                af[mi][3] = packh2(f3.x, f3.y);
            }
            uint32_t bt[2][4];
#pragma unroll
            for (int nt = 0; nt < 2; nt++)
                ldsm4(bt[nt], wOff + (uint32_t)(wn * 32 + nt * 16 + lr) * 48 + lb);
#pragma unroll
            for (int mi = 0; mi < 4; mi++)
#pragma unroll
                for (int ni = 0; ni < 4; ni++) {
                    const int nt = ni >> 1, sub = ni & 1;
                    mma16816(acc[mi][ni], af[mi], bt[nt][sub ? 1 : 0], bt[nt][sub ? 3 : 2]);
                }
            if (kt + 3 < 32) {
                const int ns = (kt + 3) & 3;
                cp16(aBase + ns * EAS + rowA * 96 + quad * 16,
                     Abase + (size_t)rowA * H_ + (kt + 3) * 16 + quad * 4);
                cp16(wBase + ns * EWS + rowW * 48 + wh * 16,
                     Wb2 + (size_t)rowW * H_ + (kt + 3) * 16 + wh * 8);
            }
            CP_COMMIT();
        }

        // epilogue for this 256-col chunk
#pragma unroll
        for (int mi = 0; mi < 4; mi++)
#pragma unroll
            for (int hf = 0; hf < 2; hf++) {
                const int rl = wm * 64 + mi * 16 + g + hf * 8;
                const float* WhR = Wh + (size_t)(b0 + rl) * H_;
                float s = 0.f;
#pragma unroll
                for (int ni = 0; ni < 4; ni++) {
                    const int col = nc * 256 + wn * 32 + ni * 8 + tg * 2;
                    float v0 = acc[mi][ni][hf * 2 + 0] + Ub[col] + WhR[col];
                    float v1 = acc[mi][ni][hf * 2 + 1] + Ub[col + 1] + WhR[col + 1];
                    s += tanhf(v0) * aw[col] + tanhf(v1) * aw[col + 1];
                }
                s += __shfl_xor_sync(0xffffffffu, s, 1);
                s += __shfl_xor_sync(0xffffffffu, s, 2);
                if (tg == 0) atomicAdd(&esum[rl], s);
            }
    }
    __syncthreads();
    if (tid < 128) energy[r0 + tid] = esum[tid] + ab[0];
}

// ============================================================
// GRU fused layer (unchanged from R9): cp.async 3-stage,
// 256 thr, tile 64 rows x 32 h-cols, merged r/z accumulators.
// ============================================================
#define GST 15360   // 320 rows * 48B per stage

template<int KI>
__global__ void __launch_bounds__(256, 2) gru_fused_kernel(
    const __half* __restrict__ AiH, const __half* __restrict__ WiH,
    const __half* __restrict__ AhH, const __half* __restrict__ WhH,
    const float* __restrict__ Ahf,
    const float* __restrict__ bi, const float* __restrict__ bh,
    float* __restrict__ hout, __half* __restrict__ houtH) {
    __shared__ __align__(16) char sm[3 * GST];

    const int tid = threadIdx.x;
    const int lane = tid & 31, wid = tid >> 5;
    const int wm = wid >> 1, wn = wid & 1;
    const int gl = lane >> 2, tg = lane & 3;
    const int lr = (lane & 7) + ((lane >> 3) & 1) * 8;
    const int lb = ((lane >> 4) & 1) * 16;
    const int m0 = blockIdx.y * 64;
    const int nb = blockIdx.x * 32;
    const uint32_t base = smem_u32(sm);

    const __half* srcp[3];
    uint32_t dsto[3];
    bool ish[3], valid[3];
#pragma unroll
    for (int i = 0; i < 3; i++) {
        const int idx = i * 256 + tid;
        valid[i] = idx < 640;
        const int row = (idx < 640) ? (idx >> 1) : 0;
        const int hf = idx & 1;
        const __half* p;
        bool h;
        if (row < 64)       { p = AiH + (size_t)(m0 + row) * KI; h = false; }
        else if (row < 128) { p = AhH + (size_t)(m0 + row - 64) * H_; h = true; }
        else if (row < 224) { const int q = row - 128; p = WiH + (size_t)((q >> 5) * H_ + nb + (q & 31)) * KI; h = false; }
        else                { const int q = row - 224; p = WhH + (size_t)((q >> 5) * H_ + nb + (q & 31)) * H_; h = true; }
        srcp[i] = p + hf * 8;
        dsto[i] = row * 48 + hf * 16;
        ish[i] = h;
    }

    float acc_rz[2][2][4] = {};
    float acc_n0[2][4] = {};
    float acc_n1[2][4] = {};

    constexpr int NKT = KI / 16;
#pragma unroll
    for (int s = 0; s < 2; s++) {
#pragma unroll
        for (int i = 0; i < 3; i++)
            if (valid[i] && (!ish[i] || s < 32))
                cp16(base + s * GST + dsto[i], srcp[i] + s * 16);
        CP_COMMIT();
    }

    for (int kt = 0; kt < NKT; kt++) {
        const int s = kt % 3;
        CP_WAIT(1);
        __syncthreads();

        const uint32_t off = base + (uint32_t)s * GST;
        const bool act_h = (kt < 32);
        uint32_t afi[4], afh[4], bwi[3][4], bwh[3][4];
        ldsm4(afi, off + (uint32_t)(wm * 16 + lr) * 48 + lb);
#pragma unroll
        for (int gt = 0; gt < 3; gt++)
            ldsm4(bwi[gt], off + (uint32_t)(128 + gt * 32 + wn * 16 + lr) * 48 + lb);
        if (act_h) {
            ldsm4(afh, off + (uint32_t)(64 + wm * 16 + lr) * 48 + lb);
#pragma unroll
            for (int gt = 0; gt < 3; gt++)
                ldsm4(bwh[gt], off + (uint32_t)(224 + gt * 32 + wn * 16 + lr) * 48 + lb);
        }
#pragma unroll
        for (int sub = 0; sub < 2; sub++) {
            mma16816(acc_rz[0][sub], afi, bwi[0][sub], bwi[0][sub + 2]);
            mma16816(acc_rz[1][sub], afi, bwi[1][sub], bwi[1][sub + 2]);
            mma16816(acc_n0[sub],    afi, bwi[2][sub], bwi[2][sub + 2]);
        }
        if (act_h) {
#pragma unroll
            for (int sub = 0; sub < 2; sub++) {
                mma16816(acc_rz[0][sub], afh, bwh[0][sub], bwh[0][sub + 2]);
                mma16816(acc_rz[1][sub], afh, bwh[1][sub], bwh[1][sub + 2]);
                mma16816(acc_n1[sub],    afh, bwh[2][sub], bwh[2][sub + 2]);
            }
        }
        if (kt + 2 < NKT) {
            const int ns = (kt + 2) % 3;
#pragma unroll
            for (int i = 0; i < 3; i++)
                if (valid[i] && (!ish[i] || (kt + 2) < 32))
                    cp16(base + ns * GST + dsto[i], srcp[i] + (kt + 2) * 16);
        }
        CP_COMMIT();
    }

#pragma unroll
    for (int hf = 0; hf < 2; hf++) {
        const int row = m0 + wm * 16 + gl + hf * 8;
#pragma unroll
        for (int sub = 0; sub < 2; sub++) {
            const int col = nb + wn * 16 + sub * 8 + tg * 2;
            float2 hp = *(const float2*)&Ahf[(size_t)row * H_ + col];
            float2 o;
#pragma unroll
            for (int j = 0; j < 2; j++) {
                const int cj = col + j;
                float rr = sigf(acc_rz[0][sub][hf * 2 + j] + bi[cj] + bh[cj]);
                float zz = sigf(acc_rz[1][sub][hf * 2 + j] + bi[H_ + cj] + bh[H_ + cj]);
                float nn = tanhf(acc_n0[sub][hf * 2 + j] + bi[2 * H_ + cj] +
                                 rr * (acc_n1[sub][hf * 2 + j] + bh[2 * H_ + cj]));
                float hv = j ? hp.y : hp.x;
                float res = fmaf(zz, hv - nn, nn);
                if (j) o.y = res; else o.x = res;
            }
            *(float2*)&hout[(size_t)row * H_ + col] = o;
            *(__half2*)&houtH[(size_t)row * H_ + col] = __float22half2_rn(o);
        }
    }
}

// ---------------- small GEMM: C[M,N] = A@W^T + bias (fp32 in, 64x64) ----------------
__global__ void __launch_bounds__(256, 2) sgemm64_kernel(
    const float* __restrict__ A, const float* __restrict__ W,
    const float* __restrict__ bias, float* __restrict__ C, int K, int N) {
    __shared__ __align__(16) __half sm[2 * 128 * 24];

    const int tid = threadIdx.x;
    const int lane = tid & 31, wid = tid >> 5;
    const int wm = wid >> 1, wn = wid & 1;
    const int g = lane >> 2, tg = lane & 3;
    const int lr = (lane & 7) + ((lane >> 3) & 1) * 8;
    const int lb = ((lane >> 4) & 1) * 16;
    const int m0 = blockIdx.y * 64, n0 = blockIdx.x * 64;
    const uint32_t base = smem_u32(sm);

    const int r = tid >> 2, c = (tid & 3) * 4;
    float acc[4][4] = {};
    float4 ra, rw;
    ra = *(const float4*)&A[(size_t)(m0 + r) * K + c];
    rw = *(const float4*)&W[(size_t)(n0 + r) * K + c];
    sts16(sm + r * 24 + c, ra);
    sts16(sm + (64 + r) * 24 + c, rw);
    __syncthreads();

    const int nk = K / 16;
    for (int kt = 0; kt < nk; kt++) {
        const int p = kt & 1;
        if (kt + 1 < nk) {
            ra = *(const float4*)&A[(size_t)(m0 + r) * K + (kt + 1) * 16 + c];
            rw = *(const float4*)&W[(size_t)(n0 + r) * K + (kt + 1) * 16 + c];
        }
        const uint32_t off = base + (uint32_t)p * 128 * 48;
        uint32_t af[4], bt[2][4];
        ldsm4(af, off + (uint32_t)(wm * 16 + lr) * 48 + lb);
#pragma unroll
        for (int nt = 0; nt < 2; nt++)
            ldsm4(bt[nt], off + (uint32_t)(64 + wn * 32 + nt * 16 + lr) * 48 + lb);
#pragma unroll
        for (int ni = 0; ni < 4; ni++) {
            const int nt = ni >> 1, sub = ni & 1;
            mma16816(acc[ni], af, bt[nt][sub ? 1 : 0], bt[nt][sub ? 3 : 2]);
        }
        if (kt + 1 < nk) {
            __half* d = sm + (p ^ 1) * 128 * 24;
            sts16(d + r * 24 + c, ra);
            sts16(d + (64 + r) * 24 + c, rw);
        }
        __syncthreads();
    }

#pragma unroll
    for (int hf = 0; hf < 2; hf++) {
        const int row = m0 + wm * 16 + g + hf * 8;
#pragma unroll
        for (int ni = 0; ni < 4; ni++) {
            const int col = n0 + wn * 32 + ni * 8 + tg * 2;
            float2 o;
            o.x = acc[ni][hf * 2 + 0] + bias[col];
            o.y = acc[ni][hf * 2 + 1] + bias[col + 1];
            *(float2*)&C[(size_t)row * N + col] = o;
        }
    }
}

// ---------------- fused softmax + context + embedding (fp16 rnn out) ----------------
__global__ void __launch_bounds__(256) attn_ctx_kernel(
    const float* __restrict__ energy, const float* __restrict__ Es,
    const int* __restrict__ x, const float* __restrict__ emb,
    __half* __restrict__ rnnH) {
    __shared__ float red[S_];
    __shared__ float att[S_];
    const int b = blockIdx.x;
    const int s = threadIdx.x;

    float v = energy[s * B_ + b];
    red[s] = v;
    __syncthreads();
    for (int off = S_ / 2; off; off >>= 1) {
        if (s < off) red[s] = fmaxf(red[s], red[s + off]);
        __syncthreads();
    }
    float m = red[0];
    __syncthreads();
    float ex = __expf(v - m);
    red[s] = ex;
    __syncthreads();
    for (int off = S_ / 2; off; off >>= 1) {
        if (s < off) red[s] += red[s + off];
        __syncthreads();
    }
    att[s] = ex / red[0];
    __syncthreads();

    const int h = s * 2;
    float cx = 0.f, cy = 0.f;
    const float* base = Es + (size_t)b * H_ + h;
#pragma unroll 4
    for (int s2 = 0; s2 < S_; s2++) {
        float a = att[s2];
        float2 e = *(const float2*)&base[(size_t)s2 * B_ * H_];
        cx = fmaf(a, e.x, cx);
        cy = fmaf(a, e.y, cy);
    }
    *(__half2*)&rnnH[(size_t)b * (H_ + E_) + h] = __float22half2_rn(make_float2(cx, cy));
    rnnH[(size_t)b * (H_ + E_) + H_ + s] = __float2half(emb[(size_t)x[b] * E_ + s]);
}

// ---------------- launch ----------------
extern "C" void kernel_launch(void* const* d_in, const int* in_sizes, int n_in,
                              void* d_out, int out_size) {
    const int*   x      = (const int*)  d_in[0];
    const float* Es     = (const float*)d_in[1];
    const float* hidden = (const float*)d_in[2];
    const float* emb    = (const float*)d_in[4];
    const float* Uw     = (const float*)d_in[5];
    const float* Ub     = (const float*)d_in[6];
    const float* Ww     = (const float*)d_in[7];
    const float* Wb     = (const float*)d_in[8];
    const float* aw     = (const float*)d_in[9];
    const float* ab     = (const float*)d_in[10];
    const float* w_ih0  = (const float*)d_in[11];
    const float* w_hh0  = (const float*)d_in[12];
    const float* b_ih0  = (const float*)d_in[13];
    const float* b_hh0  = (const float*)d_in[14];
    const float* w_ih_r = (const float*)d_in[15];
    const float* w_hh_r = (const float*)d_in[16];
    const float* b_ih_r = (const float*)d_in[17];
    const float* b_hh_r = (const float*)d_in[18];
    const float* fcw    = (const float*)d_in[19];
    const float* fcb    = (const float*)d_in[20];

    float* out     = (float*)d_out;
    float* pred    = out;               // [B, OUT]
    float* hid_out = out + B_ * OUT_;   // [L, B, H]

    float *Wh, *energy;
    __half *UwH, *WiH0, *WhH0, *WiHr, *WhHr, *hidH, *rnnH, *houtH;
    cudaGetSymbolAddress((void**)&Wh,     g_Wh);
    cudaGetSymbolAddress((void**)&energy, g_energy);
    cudaGetSymbolAddress((void**)&UwH,    g_UwH);
    cudaGetSymbolAddress((void**)&WiH0,   g_WiH0);
    cudaGetSymbolAddress((void**)&WhH0,   g_WhH0);
    cudaGetSymbolAddress((void**)&WiHr,   g_WiHr);
    cudaGetSymbolAddress((void**)&WhHr,   g_WhHr);
    cudaGetSymbolAddress((void**)&hidH,   g_hidH);
    cudaGetSymbolAddress((void**)&rnnH,   g_rnnH);
    cudaGetSymbolAddress((void**)&houtH,  g_houtH);

    cudaFuncSetAttribute(energy_async_kernel,
                         cudaFuncAttributeMaxDynamicSharedMemorySize, ESMEM_DYN);

    const float* hlast = hidden + (size_t)(L_ - 1) * B_ * H_;

    // 0) all fp32 -> fp16 conversions in one launch (no Es conversion!)
    cvt_all_kernel<<<CVT_BLOCKS, 256>>>(Uw, UwH, w_ih0, WiH0, w_hh0, WhH0,
                                        w_ih_r, WiHr, w_hh_r, WhHr, hidden, hidH);

    // 1) Wh = hidden[-1] @ Ww^T + Wb
    sgemm64_kernel<<<dim3(H_ / 64, B_ / 64), 256>>>(hlast, Ww, Wb, Wh, H_, H_);

    // 2) fused energy (fp32 A via cp.async, manual fragments)
    energy_async_kernel<<<(S_ * B_) / 128, 512, ESMEM_DYN>>>(
        Es, UwH, Ub, Wh, aw, ab, energy);

    // 3) softmax + context + embedding -> fp16 rnn
    attn_ctx_kernel<<<B_, 256>>>(energy, Es, x, emb, rnnH);

    // 4) fused GRU layers (cp.async 3-stage, merged r/z acc)
    gru_fused_kernel<768><<<dim3(H_ / 32, B_ / 64), 256>>>(
        rnnH, WiH0, hidH, WhH0, hidden, b_ih0, b_hh0, hid_out, houtH);
    for (int l = 1; l < L_; l++) {
        gru_fused_kernel<512><<<dim3(H_ / 32, B_ / 64), 256>>>(
            houtH + (size_t)(l - 1) * B_ * H_,
            WiHr + (size_t)(l - 1) * 3 * H_ * H_,
            hidH + (size_t)l * B_ * H_,
            WhHr + (size_t)(l - 1) * 3 * H_ * H_,
            hidden + (size_t)l * B_ * H_,
            b_ih_r + (size_t)(l - 1) * 3 * H_,
            b_hh_r + (size_t)(l - 1) * 3 * H_,
            hid_out + (size_t)l * B_ * H_,
            houtH + (size_t)l * B_ * H_);
    }

    // 5) predictions = h_last @ fcw^T + fcb
    sgemm64_kernel<<<dim3(OUT_ / 64, B_ / 64), 256>>>(
        hid_out + (size_t)(L_ - 1) * B_ * H_, fcw, fcb, pred, H_, OUT_);
}

// round 11
// speedup vs baseline: 1.1821x; 1.0269x over previous
#include <cuda_runtime.h>
#include <cuda_fp16.h>
#include <math.h>
#include <stdint.h>

#define S_   256
#define B_   512
#define H_   512
#define E_   256
#define L_   4
#define OUT_ 128

// ---------------- scratch (no allocs allowed) ----------------
__device__ float  g_Wh[B_ * H_];
__device__ float  g_energyT[B_ * S_];     // transposed: [b][s]
__device__ __half g_UwH[H_ * H_];
__device__ __half g_WiH0[3 * H_ * (H_ + E_)];
__device__ __half g_WhH0[3 * H_ * H_];
__device__ __half g_WiHr[(L_ - 1) * 3 * H_ * H_];
__device__ __half g_WhHr[(L_ - 1) * 3 * H_ * H_];
__device__ __half g_hidH[L_ * B_ * H_];
__device__ __half g_rnnH[B_ * (H_ + E_)];
__device__ __half g_houtH[L_ * B_ * H_];

// ---------------- helpers ----------------
__device__ __forceinline__ uint32_t smem_u32(const void* p) {
    uint32_t a;
    asm("{ .reg .u64 t; cvta.to.shared.u64 t, %1; cvt.u32.u64 %0, t; }" : "=r"(a) : "l"(p));
    return a;
}
__device__ __forceinline__ void ldsm4(uint32_t* r, uint32_t addr) {
    asm volatile("ldmatrix.sync.aligned.m8n8.x4.shared.b16 {%0,%1,%2,%3}, [%4];"
                 : "=r"(r[0]), "=r"(r[1]), "=r"(r[2]), "=r"(r[3]) : "r"(addr));
}
__device__ __forceinline__ void mma16816(float* c, const uint32_t* a, uint32_t b0, uint32_t b1) {
    asm volatile(
        "mma.sync.aligned.m16n8k16.row.col.f32.f16.f16.f32 "
        "{%0,%1,%2,%3}, {%4,%5,%6,%7}, {%8,%9}, {%0,%1,%2,%3};\n"
        : "+f"(c[0]), "+f"(c[1]), "+f"(c[2]), "+f"(c[3])
        : "r"(a[0]), "r"(a[1]), "r"(a[2]), "r"(a[3]), "r"(b0), "r"(b1));
}
__device__ __forceinline__ void cp16(uint32_t daddr, const void* saddr) {
    asm volatile("cp.async.cg.shared.global [%0], [%1], 16;" :: "r"(daddr), "l"(saddr) : "memory");
}
#define CP_COMMIT() asm volatile("cp.async.commit_group;" ::: "memory")
#define CP_WAIT(n)  asm volatile("cp.async.wait_group " #n ";" ::: "memory")

__device__ __forceinline__ void sts16(__half* dst, float4 v) {
    __half2* d = (__half2*)dst;
    d[0] = __float22half2_rn(make_float2(v.x, v.y));
    d[1] = __float22half2_rn(make_float2(v.z, v.w));
}
__device__ __forceinline__ uint32_t packh2(float a, float b) {
    __half2 h = __float22half2_rn(make_float2(a, b));
    return *reinterpret_cast<uint32_t*>(&h);
}
// Fast, accurate-enough transcendentals (explicit MUFU path regardless of
// compiler fast-math settings). abs error ~1e-6 — negligible vs fp16 GEMM.
__device__ __forceinline__ float ftanh(float x) {
    float e = __expf(2.f * x);                   // inf for big x -> 1.0 exactly
    return 1.f - __fdividef(2.f, e + 1.f);
}
__device__ __forceinline__ float fsig(float x) {
    return __fdividef(1.f, 1.f + __expf(-x));
}

// ---------------- merged fp32 -> fp16 conversions (one launch) ----------------
#define Q_UW   (H_ * H_ / 4)
#define Q_WI0  (Q_UW + 3 * H_ * (H_ + E_) / 4)
#define Q_WH0  (Q_WI0 + 3 * H_ * H_ / 4)
#define Q_WIR  (Q_WH0 + (L_ - 1) * 3 * H_ * H_ / 4)
#define Q_WHR  (Q_WIR + (L_ - 1) * 3 * H_ * H_ / 4)
#define Q_HID  (Q_WHR + L_ * B_ * H_ / 4)
#define CVT_BLOCKS (Q_HID / 256)

__global__ void cvt_all_kernel(
    const float* __restrict__ Uw,   __half* __restrict__ UwH,
    const float* __restrict__ wi0,  __half* __restrict__ WiH0,
    const float* __restrict__ wh0,  __half* __restrict__ WhH0,
    const float* __restrict__ wir,  __half* __restrict__ WiHr,
    const float* __restrict__ whr,  __half* __restrict__ WhHr,
    const float* __restrict__ hid,  __half* __restrict__ hidH) {
    const int i = blockIdx.x * 256 + threadIdx.x;
    const float* src;
    __half* dst;
    int off;
    if (i < Q_UW)       { src = Uw;  dst = UwH;  off = 0; }
    else if (i < Q_WI0) { src = wi0; dst = WiH0; off = Q_UW; }
    else if (i < Q_WH0) { src = wh0; dst = WhH0; off = Q_WI0; }
    else if (i < Q_WIR) { src = wir; dst = WiHr; off = Q_WH0; }
    else if (i < Q_WHR) { src = whr; dst = WhHr; off = Q_WIR; }
    else                { src = hid; dst = hidH; off = Q_WHR; }
    const int j = i - off;
    float4 v = ((const float4*)src)[j];
    uint2 o;
    o.x = packh2(v.x, v.y);
    o.y = packh2(v.z, v.w);
    ((uint2*)dst)[j] = o;
}

// ============================================================
// Energy kernel (same GEMM as R10): fp32 A via cp.async +
// manual fragments, fp16 B via ldsm. Epilogue uses ftanh,
// result stored TRANSPOSED energyT[b][s].
// ============================================================
#define EAS 12288
#define EWS 12288
#define ESMEM_DYN (512 + 4 * EAS + 4 * EWS)

__global__ void __launch_bounds__(512, 1) energy_async_kernel(
    const float* __restrict__ Es, const __half* __restrict__ UwH,
    const float* __restrict__ Ub, const float* __restrict__ Wh,
    const float* __restrict__ aw, const float* __restrict__ ab,
    float* __restrict__ energyT) {
    extern __shared__ __align__(16) char dsm[];
    float* esum = (float*)dsm;
    char* aRegion = dsm + 512;
    char* wRegion = dsm + 512 + 4 * EAS;
    const uint32_t aBase = smem_u32(aRegion);
    const uint32_t wBase = smem_u32(wRegion);

    const int tid = threadIdx.x;
    const int lane = tid & 31, wid = tid >> 5;
    const int wm = wid >> 3, wn = wid & 7;
    const int g = lane >> 2, tg = lane & 3;
    const int lr = (lane & 7) + ((lane >> 3) & 1) * 8;
    const int lb = ((lane >> 4) & 1) * 16;
    const int r0 = blockIdx.x * 128;
    const int b0 = r0 & (B_ - 1);

    const int rowA = tid >> 2, quad = tid & 3;
    const int rowW = tid >> 1, wh = tid & 1;

    if (tid < 128) esum[tid] = 0.f;
    __syncthreads();

    for (int nc = 0; nc < 2; nc++) {
        const float* Abase = Es + (size_t)r0 * H_;
        const __half* Wb2 = UwH + (size_t)(nc * 256) * H_;
        float acc[4][4][4] = {};

#pragma unroll
        for (int s = 0; s < 3; s++) {
            cp16(aBase + s * EAS + rowA * 96 + quad * 16,
                 Abase + (size_t)rowA * H_ + s * 16 + quad * 4);
            cp16(wBase + s * EWS + rowW * 48 + wh * 16,
                 Wb2 + (size_t)rowW * H_ + s * 16 + wh * 8);
            CP_COMMIT();
        }

        for (int kt = 0; kt < 32; kt++) {
            const int s = kt & 3;
            CP_WAIT(2);
            __syncthreads();

            const float* sA = (const float*)(aRegion + s * EAS);
            const uint32_t wOff = wBase + (uint32_t)s * EWS;

            uint32_t af[4][4];
#pragma unroll
            for (int mi = 0; mi < 4; mi++) {
                const int rb = wm * 64 + mi * 16 + g;
                float2 f0 = *(const float2*)&sA[rb * 24 + tg * 2];
                float2 f1 = *(const float2*)&sA[(rb + 8) * 24 + tg * 2];
                float2 f2 = *(const float2*)&sA[rb * 24 + tg * 2 + 8];
                float2 f3 = *(const float2*)&sA[(rb + 8) * 24 + tg * 2 + 8];
                af[mi][0] = packh2(f0.x, f0.y);
                af[mi][1] = packh2(f1.x, f1.y);
                af[mi][2] = packh2(f2.x, f2.y);
                af[mi][3] = packh2(f3.x, f3.y);
            }
            uint32_t bt[2][4];
#pragma unroll
            for (int nt = 0; nt < 2; nt++)
                ldsm4(bt[nt], wOff + (uint32_t)(wn * 32 + nt * 16 + lr) * 48 + lb);
#pragma unroll
            for (int mi = 0; mi < 4; mi++)
#pragma unroll
                for (int ni = 0; ni < 4; ni++) {
                    const int nt = ni >> 1, sub = ni & 1;
                    mma16816(acc[mi][ni], af[mi], bt[nt][sub ? 1 : 0], bt[nt][sub ? 3 : 2]);
                }
            if (kt + 3 < 32) {
                const int ns = (kt + 3) & 3;
                cp16(aBase + ns * EAS + rowA * 96 + quad * 16,
                     Abase + (size_t)rowA * H_ + (kt + 3) * 16 + quad * 4);
                cp16(wBase + ns * EWS + rowW * 48 + wh * 16,
                     Wb2 + (size_t)rowW * H_ + (kt + 3) * 16 + wh * 8);
            }
            CP_COMMIT();
        }

#pragma unroll
        for (int mi = 0; mi < 4; mi++)
#pragma unroll
            for (int hf = 0; hf < 2; hf++) {
                const int rl = wm * 64 + mi * 16 + g + hf * 8;
                const float* WhR = Wh + (size_t)(b0 + rl) * H_;
                float s = 0.f;
#pragma unroll
                for (int ni = 0; ni < 4; ni++) {
                    const int col = nc * 256 + wn * 32 + ni * 8 + tg * 2;
                    float v0 = acc[mi][ni][hf * 2 + 0] + Ub[col] + WhR[col];
                    float v1 = acc[mi][ni][hf * 2 + 1] + Ub[col + 1] + WhR[col + 1];
                    s += ftanh(v0) * aw[col] + ftanh(v1) * aw[col + 1];
                }
                s += __shfl_xor_sync(0xffffffffu, s, 1);
                s += __shfl_xor_sync(0xffffffffu, s, 2);
                if (tg == 0) atomicAdd(&esum[rl], s);
            }
    }
    __syncthreads();
    if (tid < 128) {
        const int r = r0 + tid;                 // r = s*B + b
        energyT[(size_t)(r & (B_ - 1)) * S_ + (r >> 9)] = esum[tid] + ab[0];
    }
}

// ============================================================
// GRU fused layer (unchanged from R10 except fast transcendentals)
// ============================================================
#define GST 15360

template<int KI>
__global__ void __launch_bounds__(256, 2) gru_fused_kernel(
    const __half* __restrict__ AiH, const __half* __restrict__ WiH,
    const __half* __restrict__ AhH, const __half* __restrict__ WhH,
    const float* __restrict__ Ahf,
    const float* __restrict__ bi, const float* __restrict__ bh,
    float* __restrict__ hout, __half* __restrict__ houtH) {
    __shared__ __align__(16) char sm[3 * GST];

    const int tid = threadIdx.x;
    const int lane = tid & 31, wid = tid >> 5;
    const int wm = wid >> 1, wn = wid & 1;
    const int gl = lane >> 2, tg = lane & 3;
    const int lr = (lane & 7) + ((lane >> 3) & 1) * 8;
    const int lb = ((lane >> 4) & 1) * 16;
    const int m0 = blockIdx.y * 64;
    const int nb = blockIdx.x * 32;
    const uint32_t base = smem_u32(sm);

    const __half* srcp[3];
    uint32_t dsto[3];
    bool ish[3], valid[3];
#pragma unroll
    for (int i = 0; i < 3; i++) {
        const int idx = i * 256 + tid;
        valid[i] = idx < 640;
        const int row = (idx < 640) ? (idx >> 1) : 0;
        const int hf = idx & 1;
        const __half* p;
        bool h;
        if (row < 64)       { p = AiH + (size_t)(m0 + row) * KI; h = false; }
        else if (row < 128) { p = AhH + (size_t)(m0 + row - 64) * H_; h = true; }
        else if (row < 224) { const int q = row - 128; p = WiH + (size_t)((q >> 5) * H_ + nb + (q & 31)) * KI; h = false; }
        else                { const int q = row - 224; p = WhH + (size_t)((q >> 5) * H_ + nb + (q & 31)) * H_; h = true; }
        srcp[i] = p + hf * 8;
        dsto[i] = row * 48 + hf * 16;
        ish[i] = h;
    }

    float acc_rz[2][2][4] = {};
    float acc_n0[2][4] = {};
    float acc_n1[2][4] = {};

    constexpr int NKT = KI / 16;
#pragma unroll
    for (int s = 0; s < 2; s++) {
#pragma unroll
        for (int i = 0; i < 3; i++)
            if (valid[i] && (!ish[i] || s < 32))
                cp16(base + s * GST + dsto[i], srcp[i] + s * 16);
        CP_COMMIT();
    }

    for (int kt = 0; kt < NKT; kt++) {
        const int s = kt % 3;
        CP_WAIT(1);
        __syncthreads();

        const uint32_t off = base + (uint32_t)s * GST;
        const bool act_h = (kt < 32);
        uint32_t afi[4], afh[4], bwi[3][4], bwh[3][4];
        ldsm4(afi, off + (uint32_t)(wm * 16 + lr) * 48 + lb);
#pragma unroll
        for (int gt = 0; gt < 3; gt++)
            ldsm4(bwi[gt], off + (uint32_t)(128 + gt * 32 + wn * 16 + lr) * 48 + lb);
        if (act_h) {
            ldsm4(afh, off + (uint32_t)(64 + wm * 16 + lr) * 48 + lb);
#pragma unroll
            for (int gt = 0; gt < 3; gt++)
                ldsm4(bwh[gt], off + (uint32_t)(224 + gt * 32 + wn * 16 + lr) * 48 + lb);
        }
#pragma unroll
        for (int sub = 0; sub < 2; sub++) {
            mma16816(acc_rz[0][sub], afi, bwi[0][sub], bwi[0][sub + 2]);
            mma16816(acc_rz[1][sub], afi, bwi[1][sub], bwi[1][sub + 2]);
            mma16816(acc_n0[sub],    afi, bwi[2][sub], bwi[2][sub + 2]);
        }
        if (act_h) {
#pragma unroll
            for (int sub = 0; sub < 2; sub++) {
                mma16816(acc_rz[0][sub], afh, bwh[0][sub], bwh[0][sub + 2]);
                mma16816(acc_rz[1][sub], afh, bwh[1][sub], bwh[1][sub + 2]);
                mma16816(acc_n1[sub],    afh, bwh[2][sub], bwh[2][sub + 2]);
            }
        }
        if (kt + 2 < NKT) {
            const int ns = (kt + 2) % 3;
#pragma unroll
            for (int i = 0; i < 3; i++)
                if (valid[i] && (!ish[i] || (kt + 2) < 32))
                    cp16(base + ns * GST + dsto[i], srcp[i] + (kt + 2) * 16);
        }
        CP_COMMIT();
    }

#pragma unroll
    for (int hf = 0; hf < 2; hf++) {
        const int row = m0 + wm * 16 + gl + hf * 8;
#pragma unroll
        for (int sub = 0; sub < 2; sub++) {
            const int col = nb + wn * 16 + sub * 8 + tg * 2;
            float2 hp = *(const float2*)&Ahf[(size_t)row * H_ + col];
            float2 o;
#pragma unroll
            for (int j = 0; j < 2; j++) {
                const int cj = col + j;
                float rr = fsig(acc_rz[0][sub][hf * 2 + j] + bi[cj] + bh[cj]);
                float zz = fsig(acc_rz[1][sub][hf * 2 + j] + bi[H_ + cj] + bh[H_ + cj]);
                float nn = ftanh(acc_n0[sub][hf * 2 + j] + bi[2 * H_ + cj] +
                                 rr * (acc_n1[sub][hf * 2 + j] + bh[2 * H_ + cj]));
                float hv = j ? hp.y : hp.x;
                float res = fmaf(zz, hv - nn, nn);
                if (j) o.y = res; else o.x = res;
            }
            *(float2*)&hout[(size_t)row * H_ + col] = o;
            *(__half2*)&houtH[(size_t)row * H_ + col] = __float22half2_rn(o);
        }
    }
}

// ---------------- small GEMM: C[M,N] = A@W^T + bias (fp32 in, 64x64) ----------------
__global__ void __launch_bounds__(256, 2) sgemm64_kernel(
    const float* __restrict__ A, const float* __restrict__ W,
    const float* __restrict__ bias, float* __restrict__ C, int K, int N) {
    __shared__ __align__(16) __half sm[2 * 128 * 24];

    const int tid = threadIdx.x;
    const int lane = tid & 31, wid = tid >> 5;
    const int wm = wid >> 1, wn = wid & 1;
    const int g = lane >> 2, tg = lane & 3;
    const int lr = (lane & 7) + ((lane >> 3) & 1) * 8;
    const int lb = ((lane >> 4) & 1) * 16;
    const int m0 = blockIdx.y * 64, n0 = blockIdx.x * 64;
    const uint32_t base = smem_u32(sm);

    const int r = tid >> 2, c = (tid & 3) * 4;
    float acc[4][4] = {};
    float4 ra, rw;
    ra = *(const float4*)&A[(size_t)(m0 + r) * K + c];
    rw = *(const float4*)&W[(size_t)(n0 + r) * K + c];
    sts16(sm + r * 24 + c, ra);
    sts16(sm + (64 + r) * 24 + c, rw);
    __syncthreads();

    const int nk = K / 16;
    for (int kt = 0; kt < nk; kt++) {
        const int p = kt & 1;
        if (kt + 1 < nk) {
            ra = *(const float4*)&A[(size_t)(m0 + r) * K + (kt + 1) * 16 + c];
            rw = *(const float4*)&W[(size_t)(n0 + r) * K + (kt + 1) * 16 + c];
        }
        const uint32_t off = base + (uint32_t)p * 128 * 48;
        uint32_t af[4], bt[2][4];
        ldsm4(af, off + (uint32_t)(wm * 16 + lr) * 48 + lb);
#pragma unroll
        for (int nt = 0; nt < 2; nt++)
            ldsm4(bt[nt], off + (uint32_t)(64 + wn * 32 + nt * 16 + lr) * 48 + lb);
#pragma unroll
        for (int ni = 0; ni < 4; ni++) {
            const int nt = ni >> 1, sub = ni & 1;
            mma16816(acc[ni], af, bt[nt][sub ? 1 : 0], bt[nt][sub ? 3 : 2]);
        }
        if (kt + 1 < nk) {
            __half* d = sm + (p ^ 1) * 128 * 24;
            sts16(d + r * 24 + c, ra);
            sts16(d + (64 + r) * 24 + c, rw);
        }
        __syncthreads();
    }

#pragma unroll
    for (int hf = 0; hf < 2; hf++) {
        const int row = m0 + wm * 16 + g + hf * 8;
#pragma unroll
        for (int ni = 0; ni < 4; ni++) {
            const int col = n0 + wn * 32 + ni * 8 + tg * 2;
            float2 o;
            o.x = acc[ni][hf * 2 + 0] + bias[col];
            o.y = acc[ni][hf * 2 + 1] + bias[col + 1];
            *(float2*)&C[(size_t)row * N + col] = o;
        }
    }
}

// ============================================================
// attn+context+emb: grid (4, B), 128 threads. Each block
// recomputes softmax (contiguous energyT row), then handles a
// 128-wide h-slice of the context with one float per thread.
// ============================================================
__global__ void __launch_bounds__(128) attn_ctx_kernel(
    const float* __restrict__ energyT, const float* __restrict__ Es,
    const int* __restrict__ x, const float* __restrict__ emb,
    __half* __restrict__ rnnH) {
    __shared__ float sv[S_];
    __shared__ float att[S_];
    const int q = blockIdx.x;
    const int b = blockIdx.y;
    const int t = threadIdx.x;

    float e0 = energyT[(size_t)b * S_ + t];
    float e1 = energyT[(size_t)b * S_ + 128 + t];
    sv[t] = fmaxf(e0, e1);
    __syncthreads();
    for (int off = 64; off; off >>= 1) {
        if (t < off) sv[t] = fmaxf(sv[t], sv[t + off]);
        __syncthreads();
    }
    const float m = sv[0];
    __syncthreads();
    float x0 = __expf(e0 - m), x1 = __expf(e1 - m);
    att[t] = x0;
    att[t + 128] = x1;
    sv[t] = x0 + x1;
    __syncthreads();
    for (int off = 64; off; off >>= 1) {
        if (t < off) sv[t] += sv[t + off];
        __syncthreads();
    }
    const float inv = __fdividef(1.f, sv[0]);
    __syncthreads();

    // context: h = q*128 + t
    const int h = q * 128 + t;
    const float* base = Es + (size_t)b * H_ + h;
    float a0 = 0.f, a1 = 0.f, a2 = 0.f, a3 = 0.f;
#pragma unroll 2
    for (int s = 0; s < S_; s += 4) {
        a0 = fmaf(att[s + 0], base[(size_t)(s + 0) * B_ * H_], a0);
        a1 = fmaf(att[s + 1], base[(size_t)(s + 1) * B_ * H_], a1);
        a2 = fmaf(att[s + 2], base[(size_t)(s + 2) * B_ * H_], a2);
        a3 = fmaf(att[s + 3], base[(size_t)(s + 3) * B_ * H_], a3);
    }
    rnnH[(size_t)b * (H_ + E_) + h] = __float2half(((a0 + a1) + (a2 + a3)) * inv);

    // embedding: each block writes its 64-wide slice
    if (t < 64) {
        const int col = q * 64 + t;
        rnnH[(size_t)b * (H_ + E_) + H_ + col] = __float2half(emb[(size_t)x[b] * E_ + col]);
    }
}

// ---------------- launch ----------------
extern "C" void kernel_launch(void* const* d_in, const int* in_sizes, int n_in,
                              void* d_out, int out_size) {
    const int*   x      = (const int*)  d_in[0];
    const float* Es     = (const float*)d_in[1];
    const float* hidden = (const float*)d_in[2];
    const float* emb    = (const float*)d_in[4];
    const float* Uw     = (const float*)d_in[5];
    const float* Ub     = (const float*)d_in[6];
    const float* Ww     = (const float*)d_in[7];
    const float* Wb     = (const float*)d_in[8];
    const float* aw     = (const float*)d_in[9];
    const float* ab     = (const float*)d_in[10];
    const float* w_ih0  = (const float*)d_in[11];
    const float* w_hh0  = (const float*)d_in[12];
    const float* b_ih0  = (const float*)d_in[13];
    const float* b_hh0  = (const float*)d_in[14];
    const float* w_ih_r = (const float*)d_in[15];
    const float* w_hh_r = (const float*)d_in[16];
    const float* b_ih_r = (const float*)d_in[17];
    const float* b_hh_r = (const float*)d_in[18];
    const float* fcw    = (const float*)d_in[19];
    const float* fcb    = (const float*)d_in[20];

    float* out     = (float*)d_out;
    float* pred    = out;               // [B, OUT]
    float* hid_out = out + B_ * OUT_;   // [L, B, H]

    float *Wh, *energyT;
    __half *UwH, *WiH0, *WhH0, *WiHr, *WhHr, *hidH, *rnnH, *houtH;
    cudaGetSymbolAddress((void**)&Wh,      g_Wh);
    cudaGetSymbolAddress((void**)&energyT, g_energyT);
    cudaGetSymbolAddress((void**)&UwH,     g_UwH);
    cudaGetSymbolAddress((void**)&WiH0,    g_WiH0);
    cudaGetSymbolAddress((void**)&WhH0,    g_WhH0);
    cudaGetSymbolAddress((void**)&WiHr,    g_WiHr);
    cudaGetSymbolAddress((void**)&WhHr,    g_WhHr);
    cudaGetSymbolAddress((void**)&hidH,    g_hidH);
    cudaGetSymbolAddress((void**)&rnnH,    g_rnnH);
    cudaGetSymbolAddress((void**)&houtH,   g_houtH);

    cudaFuncSetAttribute(energy_async_kernel,
                         cudaFuncAttributeMaxDynamicSharedMemorySize, ESMEM_DYN);

    const float* hlast = hidden + (size_t)(L_ - 1) * B_ * H_;

    // 0) all fp32 -> fp16 conversions in one launch
    cvt_all_kernel<<<CVT_BLOCKS, 256>>>(Uw, UwH, w_ih0, WiH0, w_hh0, WhH0,
                                        w_ih_r, WiHr, w_hh_r, WhHr, hidden, hidH);

    // 1) Wh = hidden[-1] @ Ww^T + Wb
    sgemm64_kernel<<<dim3(H_ / 64, B_ / 64), 256>>>(hlast, Ww, Wb, Wh, H_, H_);

    // 2) fused energy -> energyT[b][s]
    energy_async_kernel<<<(S_ * B_) / 128, 512, ESMEM_DYN>>>(
        Es, UwH, Ub, Wh, aw, ab, energyT);

    // 3) softmax + context + embedding -> fp16 rnn (grid (4, B))
    attn_ctx_kernel<<<dim3(4, B_), 128>>>(energyT, Es, x, emb, rnnH);

    // 4) fused GRU layers
    gru_fused_kernel<768><<<dim3(H_ / 32, B_ / 64), 256>>>(
        rnnH, WiH0, hidH, WhH0, hidden, b_ih0, b_hh0, hid_out, houtH);
    for (int l = 1; l < L_; l++) {
        gru_fused_kernel<512><<<dim3(H_ / 32, B_ / 64), 256>>>(
            houtH + (size_t)(l - 1) * B_ * H_,
            WiHr + (size_t)(l - 1) * 3 * H_ * H_,
            hidH + (size_t)l * B_ * H_,
            WhHr + (size_t)(l - 1) * 3 * H_ * H_,
            hidden + (size_t)l * B_ * H_,
            b_ih_r + (size_t)(l - 1) * 3 * H_,
            b_hh_r + (size_t)(l - 1) * 3 * H_,
            hid_out + (size_t)l * B_ * H_,
            houtH + (size_t)l * B_ * H_);
    }

    // 5) predictions = h_last @ fcw^T + fcb
    sgemm64_kernel<<<dim3(OUT_ / 64, B_ / 64), 256>>>(
        hid_out + (size_t)(L_ - 1) * B_ * H_, fcw, fcb, pred, H_, OUT_);
}

// round 13
// speedup vs baseline: 1.2630x; 1.0685x over previous
#include <cuda_runtime.h>
#include <cuda_fp16.h>
#include <math.h>
#include <stdint.h>

#define S_   256
#define B_   512
#define H_   512
#define E_   256
#define L_   4
#define OUT_ 128

// ---------------- scratch (no allocs allowed) ----------------
__device__ float  g_Wh[B_ * H_];
__device__ float  g_energyT[B_ * S_];     // transposed: [b][s]
__device__ __half g_UwH[H_ * H_];
__device__ __half g_WiH0[3 * H_ * (H_ + E_)];
__device__ __half g_WhH0[3 * H_ * H_];
__device__ __half g_WiHr[(L_ - 1) * 3 * H_ * H_];
__device__ __half g_WhHr[(L_ - 1) * 3 * H_ * H_];
__device__ __half g_hidH[L_ * B_ * H_];
__device__ __half g_rnnH[B_ * (H_ + E_)];
__device__ __half g_houtH[L_ * B_ * H_];

// ---------------- helpers ----------------
__device__ __forceinline__ uint32_t smem_u32(const void* p) {
    uint32_t a;
    asm("{ .reg .u64 t; cvta.to.shared.u64 t, %1; cvt.u32.u64 %0, t; }" : "=r"(a) : "l"(p));
    return a;
}
__device__ __forceinline__ void ldsm4(uint32_t* r, uint32_t addr) {
    asm volatile("ldmatrix.sync.aligned.m8n8.x4.shared.b16 {%0,%1,%2,%3}, [%4];"
                 : "=r"(r[0]), "=r"(r[1]), "=r"(r[2]), "=r"(r[3]) : "r"(addr));
}
__device__ __forceinline__ void mma16816(float* c, const uint32_t* a, uint32_t b0, uint32_t b1) {
    asm volatile(
        "mma.sync.aligned.m16n8k16.row.col.f32.f16.f16.f32 "
        "{%0,%1,%2,%3}, {%4,%5,%6,%7}, {%8,%9}, {%0,%1,%2,%3};\n"
        : "+f"(c[0]), "+f"(c[1]), "+f"(c[2]), "+f"(c[3])
        : "r"(a[0]), "r"(a[1]), "r"(a[2]), "r"(a[3]), "r"(b0), "r"(b1));
}
__device__ __forceinline__ void cp16(uint32_t daddr, const void* saddr) {
    asm volatile("cp.async.cg.shared.global [%0], [%1], 16;" :: "r"(daddr), "l"(saddr) : "memory");
}
#define CP_COMMIT() asm volatile("cp.async.commit_group;" ::: "memory")
#define CP_WAIT(n)  asm volatile("cp.async.wait_group " #n ";" ::: "memory")

__device__ __forceinline__ void sts16(__half* dst, float4 v) {
    __half2* d = (__half2*)dst;
    d[0] = __float22half2_rn(make_float2(v.x, v.y));
    d[1] = __float22half2_rn(make_float2(v.z, v.w));
}
__device__ __forceinline__ uint32_t packh2(float a, float b) {
    __half2 h = __float22half2_rn(make_float2(a, b));
    return *reinterpret_cast<uint32_t*>(&h);
}
__device__ __forceinline__ float ftanh(float x) {
    float e = __expf(2.f * x);
    return 1.f - __fdividef(2.f, e + 1.f);
}
__device__ __forceinline__ float fsig(float x) {
    return __fdividef(1.f, 1.f + __expf(-x));
}

// ---------------- merged fp32 -> fp16 conversions (one launch) ----------------
#define Q_UW   (H_ * H_ / 4)
#define Q_WI0  (Q_UW + 3 * H_ * (H_ + E_) / 4)
#define Q_WH0  (Q_WI0 + 3 * H_ * H_ / 4)
#define Q_WIR  (Q_WH0 + (L_ - 1) * 3 * H_ * H_ / 4)
#define Q_WHR  (Q_WIR + (L_ - 1) * 3 * H_ * H_ / 4)
#define Q_HID  (Q_WHR + L_ * B_ * H_ / 4)
#define CVT_BLOCKS (Q_HID / 256)

__global__ void cvt_all_kernel(
    const float* __restrict__ Uw,   __half* __restrict__ UwH,
    const float* __restrict__ wi0,  __half* __restrict__ WiH0,
    const float* __restrict__ wh0,  __half* __restrict__ WhH0,
    const float* __restrict__ wir,  __half* __restrict__ WiHr,
    const float* __restrict__ whr,  __half* __restrict__ WhHr,
    const float* __restrict__ hid,  __half* __restrict__ hidH) {
    const int i = blockIdx.x * 256 + threadIdx.x;
    const float* src;
    __half* dst;
    int off;
    if (i < Q_UW)       { src = Uw;  dst = UwH;  off = 0; }
    else if (i < Q_WI0) { src = wi0; dst = WiH0; off = Q_UW; }
    else if (i < Q_WH0) { src = wh0; dst = WhH0; off = Q_WI0; }
    else if (i < Q_WIR) { src = wir; dst = WiHr; off = Q_WH0; }
    else if (i < Q_WHR) { src = whr; dst = WhHr; off = Q_WIR; }
    else                { src = hid; dst = hidH; off = Q_WHR; }
    const int j = i - off;
    float4 v = ((const float4*)src)[j];
    uint2 o;
    o.x = packh2(v.x, v.y);
    o.y = packh2(v.z, v.w);
    ((uint2*)dst)[j] = o;
}

// ============================================================
// Energy kernel: 32-k iterations, 3-stage cp.async pipeline.
// A fp32 (rows 160B, conflict-free LDS.64), W fp16 (rows 80B,
// conflict-free ldsm). 512 thr, 16 warps (2m x 8n), warp 64x32.
// Result stored transposed energyT[b][s].
// ============================================================
#define EASZ 20480                  // A: 128 rows * 160B
#define EWSZ 20480                  // W: 256 rows * 80B
#define ESTG (EASZ + EWSZ)          // 40960 per stage
#define ESMEM_DYN (512 + 3 * ESTG)  // 123392

__global__ void __launch_bounds__(512, 1) energy_async_kernel(
    const float* __restrict__ Es, const __half* __restrict__ UwH,
    const float* __restrict__ Ub, const float* __restrict__ Wh,
    const float* __restrict__ aw, const float* __restrict__ ab,
    float* __restrict__ energyT) {
    extern __shared__ __align__(16) char dsm[];
    float* esum = (float*)dsm;
    char* tiles = dsm + 512;
    const uint32_t tBase = smem_u32(tiles);

    const int tid = threadIdx.x;
    const int lane = tid & 31, wid = tid >> 5;
    const int wm = wid >> 3, wn = wid & 7;
    const int g = lane >> 2, tg = lane & 3;
    const int lr = (lane & 7) + ((lane >> 3) & 1) * 8;
    const int lb = ((lane >> 4) & 1) * 16;
    const int r0 = blockIdx.x * 128;
    const int b0 = r0 & (B_ - 1);

    // fill mappings (2 cp16 per thread per matrix per iter)
    const int aRow0 = tid >> 3, aQ0 = tid & 7;            // idx = tid
    const int aRow1 = (tid + 512) >> 3, aQ1 = (tid + 512) & 7;
    const int wRow0 = tid >> 2, wQ0 = tid & 3;
    const int wRow1 = (tid + 512) >> 2, wQ1 = (tid + 512) & 3;

    if (tid < 128) esum[tid] = 0.f;
    __syncthreads();

    for (int nc = 0; nc < 2; nc++) {
        const float* Abase = Es + (size_t)r0 * H_;
        const __half* Wb2 = UwH + (size_t)(nc * 256) * H_;
        float acc[4][4][4] = {};

        // prologue: stages 0,1 (iters 0,1)
#pragma unroll
        for (int s = 0; s < 2; s++) {
            const uint32_t sb = tBase + (uint32_t)s * ESTG;
            cp16(sb + aRow0 * 160 + aQ0 * 16, Abase + (size_t)aRow0 * H_ + s * 32 + aQ0 * 4);
            cp16(sb + aRow1 * 160 + aQ1 * 16, Abase + (size_t)aRow1 * H_ + s * 32 + aQ1 * 4);
            cp16(sb + EASZ + wRow0 * 80 + wQ0 * 16, Wb2 + (size_t)wRow0 * H_ + s * 32 + wQ0 * 8);
            cp16(sb + EASZ + wRow1 * 80 + wQ1 * 16, Wb2 + (size_t)wRow1 * H_ + s * 32 + wQ1 * 8);
            CP_COMMIT();
        }

        for (int it = 0; it < 16; it++) {
            const int s = it % 3;
            CP_WAIT(1);
            __syncthreads();

            const float* sA = (const float*)(tiles + s * ESTG);
            const uint32_t wOff = tBase + (uint32_t)s * ESTG + EASZ;

#pragma unroll
            for (int ks = 0; ks < 2; ks++) {
                uint32_t af[4][4];
#pragma unroll
                for (int mi = 0; mi < 4; mi++) {
                    const int rb = wm * 64 + mi * 16 + g;
                    const int cb = ks * 16 + tg * 2;
                    float2 f0 = *(const float2*)&sA[rb * 40 + cb];
                    float2 f1 = *(const float2*)&sA[(rb + 8) * 40 + cb];
                    float2 f2 = *(const float2*)&sA[rb * 40 + cb + 8];
                    float2 f3 = *(const float2*)&sA[(rb + 8) * 40 + cb + 8];
                    af[mi][0] = packh2(f0.x, f0.y);
                    af[mi][1] = packh2(f1.x, f1.y);
                    af[mi][2] = packh2(f2.x, f2.y);
                    af[mi][3] = packh2(f3.x, f3.y);
                }
                uint32_t bt[2][4];
#pragma unroll
                for (int nt = 0; nt < 2; nt++)
                    ldsm4(bt[nt], wOff + (uint32_t)(wn * 32 + nt * 16 + lr) * 80 + ks * 32 + lb);
#pragma unroll
                for (int mi = 0; mi < 4; mi++)
#pragma unroll
                    for (int ni = 0; ni < 4; ni++) {
                        const int nt = ni >> 1, sub = ni & 1;
                        mma16816(acc[mi][ni], af[mi], bt[nt][sub ? 1 : 0], bt[nt][sub ? 3 : 2]);
                    }
            }
            if (it + 2 < 16) {
                const int ns = (it + 2) % 3;
                const uint32_t sb = tBase + (uint32_t)ns * ESTG;
                cp16(sb + aRow0 * 160 + aQ0 * 16, Abase + (size_t)aRow0 * H_ + (it + 2) * 32 + aQ0 * 4);
                cp16(sb + aRow1 * 160 + aQ1 * 16, Abase + (size_t)aRow1 * H_ + (it + 2) * 32 + aQ1 * 4);
                cp16(sb + EASZ + wRow0 * 80 + wQ0 * 16, Wb2 + (size_t)wRow0 * H_ + (it + 2) * 32 + wQ0 * 8);
                cp16(sb + EASZ + wRow1 * 80 + wQ1 * 16, Wb2 + (size_t)wRow1 * H_ + (it + 2) * 32 + wQ1 * 8);
            }
            CP_COMMIT();
        }

        // epilogue for this 256-col chunk
#pragma unroll
        for (int mi = 0; mi < 4; mi++)
#pragma unroll
            for (int hf = 0; hf < 2; hf++) {
                const int rl = wm * 64 + mi * 16 + g + hf * 8;
                const float* WhR = Wh + (size_t)(b0 + rl) * H_;
                float s = 0.f;
#pragma unroll
                for (int ni = 0; ni < 4; ni++) {
                    const int col = nc * 256 + wn * 32 + ni * 8 + tg * 2;
                    float v0 = acc[mi][ni][hf * 2 + 0] + Ub[col] + WhR[col];
                    float v1 = acc[mi][ni][hf * 2 + 1] + Ub[col + 1] + WhR[col + 1];
                    s += ftanh(v0) * aw[col] + ftanh(v1) * aw[col + 1];
                }
                s += __shfl_xor_sync(0xffffffffu, s, 1);
                s += __shfl_xor_sync(0xffffffffu, s, 2);
                if (tg == 0) atomicAdd(&esum[rl], s);
            }
        __syncthreads();   // stage 0 is re-written by next nc's prologue
    }
    if (tid < 128) {
        const int r = r0 + tid;                 // r = s*B + b
        energyT[(size_t)(r & (B_ - 1)) * S_ + (r >> 9)] = esum[tid] + ab[0];
    }
}

// ============================================================
// GRU fused layer (unchanged from R11)
// ============================================================
#define GST 15360

template<int KI>
__global__ void __launch_bounds__(256, 2) gru_fused_kernel(
    const __half* __restrict__ AiH, const __half* __restrict__ WiH,
    const __half* __restrict__ AhH, const __half* __restrict__ WhH,
    const float* __restrict__ Ahf,
    const float* __restrict__ bi, const float* __restrict__ bh,
    float* __restrict__ hout, __half* __restrict__ houtH) {
    __shared__ __align__(16) char sm[3 * GST];

    const int tid = threadIdx.x;
    const int lane = tid & 31, wid = tid >> 5;
    const int wm = wid >> 1, wn = wid & 1;
    const int gl = lane >> 2, tg = lane & 3;
    const int lr = (lane & 7) + ((lane >> 3) & 1) * 8;
    const int lb = ((lane >> 4) & 1) * 16;
    const int m0 = blockIdx.y * 64;
    const int nb = blockIdx.x * 32;
    const uint32_t base = smem_u32(sm);

    const __half* srcp[3];
    uint32_t dsto[3];
    bool ish[3], valid[3];
#pragma unroll
    for (int i = 0; i < 3; i++) {
        const int idx = i * 256 + tid;
        valid[i] = idx < 640;
        const int row = (idx < 640) ? (idx >> 1) : 0;
        const int hf = idx & 1;
        const __half* p;
        bool h;
        if (row < 64)       { p = AiH + (size_t)(m0 + row) * KI; h = false; }
        else if (row < 128) { p = AhH + (size_t)(m0 + row - 64) * H_; h = true; }
        else if (row < 224) { const int q = row - 128; p = WiH + (size_t)((q >> 5) * H_ + nb + (q & 31)) * KI; h = false; }
        else                { const int q = row - 224; p = WhH + (size_t)((q >> 5) * H_ + nb + (q & 31)) * H_; h = true; }
        srcp[i] = p + hf * 8;
        dsto[i] = row * 48 + hf * 16;
        ish[i] = h;
    }

    float acc_rz[2][2][4] = {};
    float acc_n0[2][4] = {};
    float acc_n1[2][4] = {};

    constexpr int NKT = KI / 16;
#pragma unroll
    for (int s = 0; s < 2; s++) {
#pragma unroll
        for (int i = 0; i < 3; i++)
            if (valid[i] && (!ish[i] || s < 32))
                cp16(base + s * GST + dsto[i], srcp[i] + s * 16);
        CP_COMMIT();
    }

    for (int kt = 0; kt < NKT; kt++) {
        const int s = kt % 3;
        CP_WAIT(1);
        __syncthreads();

        const uint32_t off = base + (uint32_t)s * GST;
        const bool act_h = (kt < 32);
        uint32_t afi[4], afh[4], bwi[3][4], bwh[3][4];
        ldsm4(afi, off + (uint32_t)(wm * 16 + lr) * 48 + lb);
#pragma unroll
        for (int gt = 0; gt < 3; gt++)
            ldsm4(bwi[gt], off + (uint32_t)(128 + gt * 32 + wn * 16 + lr) * 48 + lb);
        if (act_h) {
            ldsm4(afh, off + (uint32_t)(64 + wm * 16 + lr) * 48 + lb);
#pragma unroll
            for (int gt = 0; gt < 3; gt++)
                ldsm4(bwh[gt], off + (uint32_t)(224 + gt * 32 + wn * 16 + lr) * 48 + lb);
        }
#pragma unroll
        for (int sub = 0; sub < 2; sub++) {
            mma16816(acc_rz[0][sub], afi, bwi[0][sub], bwi[0][sub + 2]);
            mma16816(acc_rz[1][sub], afi, bwi[1][sub], bwi[1][sub + 2]);
            mma16816(acc_n0[sub],    afi, bwi[2][sub], bwi[2][sub + 2]);
        }
        if (act_h) {
#pragma unroll
            for (int sub = 0; sub < 2; sub++) {
                mma16816(acc_rz[0][sub], afh, bwh[0][sub], bwh[0][sub + 2]);
                mma16816(acc_rz[1][sub], afh, bwh[1][sub], bwh[1][sub + 2]);
                mma16816(acc_n1[sub],    afh, bwh[2][sub], bwh[2][sub + 2]);
            }
        }
        if (kt + 2 < NKT) {
            const int ns = (kt + 2) % 3;
#pragma unroll
            for (int i = 0; i < 3; i++)
                if (valid[i] && (!ish[i] || (kt + 2) < 32))
                    cp16(base + ns * GST + dsto[i], srcp[i] + (kt + 2) * 16);
        }
        CP_COMMIT();
    }

#pragma unroll
    for (int hf = 0; hf < 2; hf++) {
        const int row = m0 + wm * 16 + gl + hf * 8;
#pragma unroll
        for (int sub = 0; sub < 2; sub++) {
            const int col = nb + wn * 16 + sub * 8 + tg * 2;
            float2 hp = *(const float2*)&Ahf[(size_t)row * H_ + col];
            float2 o;
#pragma unroll
            for (int j = 0; j < 2; j++) {
                const int cj = col + j;
                float rr = fsig(acc_rz[0][sub][hf * 2 + j] + bi[cj] + bh[cj]);
                float zz = fsig(acc_rz[1][sub][hf * 2 + j] + bi[H_ + cj] + bh[H_ + cj]);
                float nn = ftanh(acc_n0[sub][hf * 2 + j] + bi[2 * H_ + cj] +
                                 rr * (acc_n1[sub][hf * 2 + j] + bh[2 * H_ + cj]));
                float hv = j ? hp.y : hp.x;
                float res = fmaf(zz, hv - nn, nn);
                if (j) o.y = res; else o.x = res;
            }
            *(float2*)&hout[(size_t)row * H_ + col] = o;
            *(__half2*)&houtH[(size_t)row * H_ + col] = __float22half2_rn(o);
        }
    }
}

// ---------------- small GEMM: C[M,N] = A@W^T + bias (fp32 in, 64x64) ----------------
__global__ void __launch_bounds__(256, 2) sgemm64_kernel(
    const float* __restrict__ A, const float* __restrict__ W,
    const float* __restrict__ bias, float* __restrict__ C, int K, int N) {
    __shared__ __align__(16) __half sm[2 * 128 * 24];

    const int tid = threadIdx.x;
    const int lane = tid & 31, wid = tid >> 5;
    const int wm = wid >> 1, wn = wid & 1;
    const int g = lane >> 2, tg = lane & 3;
    const int lr = (lane & 7) + ((lane >> 3) & 1) * 8;
    const int lb = ((lane >> 4) & 1) * 16;
    const int m0 = blockIdx.y * 64, n0 = blockIdx.x * 64;
    const uint32_t base = smem_u32(sm);

    const int r = tid >> 2, c = (tid & 3) * 4;
    float acc[4][4] = {};
    float4 ra, rw;
    ra = *(const float4*)&A[(size_t)(m0 + r) * K + c];
    rw = *(const float4*)&W[(size_t)(n0 + r) * K + c];
    sts16(sm + r * 24 + c, ra);
    sts16(sm + (64 + r) * 24 + c, rw);
    __syncthreads();

    const int nk = K / 16;
    for (int kt = 0; kt < nk; kt++) {
        const int p = kt & 1;
        if (kt + 1 < nk) {
            ra = *(const float4*)&A[(size_t)(m0 + r) * K + (kt + 1) * 16 + c];
            rw = *(const float4*)&W[(size_t)(n0 + r) * K + (kt + 1) * 16 + c];
        }
        const uint32_t off = base + (uint32_t)p * 128 * 48;
        uint32_t af[4], bt[2][4];
        ldsm4(af, off + (uint32_t)(wm * 16 + lr) * 48 + lb);
#pragma unroll
        for (int nt = 0; nt < 2; nt++)
            ldsm4(bt[nt], off + (uint32_t)(64 + wn * 32 + nt * 16 + lr) * 48 + lb);
#pragma unroll
        for (int ni = 0; ni < 4; ni++) {
            const int nt = ni >> 1, sub = ni & 1;
            mma16816(acc[ni], af, bt[nt][sub ? 1 : 0], bt[nt][sub ? 3 : 2]);
        }
        if (kt + 1 < nk) {
            __half* d = sm + (p ^ 1) * 128 * 24;
            sts16(d + r * 24 + c, ra);
            sts16(d + (64 + r) * 24 + c, rw);
        }
        __syncthreads();
    }

#pragma unroll
    for (int hf = 0; hf < 2; hf++) {
        const int row = m0 + wm * 16 + g + hf * 8;
#pragma unroll
        for (int ni = 0; ni < 4; ni++) {
            const int col = n0 + wn * 32 + ni * 8 + tg * 2;
            float2 o;
            o.x = acc[ni][hf * 2 + 0] + bias[col];
            o.y = acc[ni][hf * 2 + 1] + bias[col + 1];
            *(float2*)&C[(size_t)row * N + col] = o;
        }
    }
}

// ============================================================
// attn+context+emb: grid (2, B), 128 threads, float2 context.
// ============================================================
__global__ void __launch_bounds__(128) attn_ctx_kernel(
    const float* __restrict__ energyT, const float* __restrict__ Es,
    const int* __restrict__ x, const float* __restrict__ emb,
    __half* __restrict__ rnnH) {
    __shared__ float sv[S_];
    __shared__ float att[S_];
    const int q = blockIdx.x;
    const int b = blockIdx.y;
    const int t = threadIdx.x;

    float e0 = energyT[(size_t)b * S_ + t];
    float e1 = energyT[(size_t)b * S_ + 128 + t];
    sv[t] = fmaxf(e0, e1);
    __syncthreads();
    for (int off = 64; off; off >>= 1) {
        if (t < off) sv[t] = fmaxf(sv[t], sv[t + off]);
        __syncthreads();
    }
    const float m = sv[0];
    __syncthreads();
    float x0 = __expf(e0 - m), x1 = __expf(e1 - m);
    att[t] = x0;
    att[t + 128] = x1;
    sv[t] = x0 + x1;
    __syncthreads();
    for (int off = 64; off; off >>= 1) {
        if (t < off) sv[t] += sv[t + off];
        __syncthreads();
    }
    const float inv = __fdividef(1.f, sv[0]);
    __syncthreads();

    // context: h = q*256 + t*2 (float2)
    const int h = q * 256 + t * 2;
    const float* base = Es + (size_t)b * H_ + h;
    float ax = 0.f, ay = 0.f, bx = 0.f, by = 0.f;
#pragma unroll 2
    for (int s = 0; s < S_; s += 4) {
        float2 e0v = *(const float2*)&base[(size_t)(s + 0) * B_ * H_];
        float2 e1v = *(const float2*)&base[(size_t)(s + 1) * B_ * H_];
        float2 e2v = *(const float2*)&base[(size_t)(s + 2) * B_ * H_];
        float2 e3v = *(const float2*)&base[(size_t)(s + 3) * B_ * H_];
        ax = fmaf(att[s + 0], e0v.x, ax); ay = fmaf(att[s + 0], e0v.y, ay);
        bx = fmaf(att[s + 1], e1v.x, bx); by = fmaf(att[s + 1], e1v.y, by);
        ax = fmaf(att[s + 2], e2v.x, ax); ay = fmaf(att[s + 2], e2v.y, ay);
        bx = fmaf(att[s + 3], e3v.x, bx); by = fmaf(att[s + 3], e3v.y, by);
    }
    *(__half2*)&rnnH[(size_t)b * (H_ + E_) + h] =
        __float22half2_rn(make_float2((ax + bx) * inv, (ay + by) * inv));

    // embedding: 2 blocks x 128 threads cover E_=256
    const int col = q * 128 + t;
    rnnH[(size_t)b * (H_ + E_) + H_ + col] = __float2half(emb[(size_t)x[b] * E_ + col]);
}

// ---------------- launch ----------------
extern "C" void kernel_launch(void* const* d_in, const int* in_sizes, int n_in,
                              void* d_out, int out_size) {
    const int*   x      = (const int*)  d_in[0];
    const float* Es     = (const float*)d_in[1];
    const float* hidden = (const float*)d_in[2];
    const float* emb    = (const float*)d_in[4];
    const float* Uw     = (const float*)d_in[5];
    const float* Ub     = (const float*)d_in[6];
    const float* Ww     = (const float*)d_in[7];
    const float* Wb     = (const float*)d_in[8];
    const float* aw     = (const float*)d_in[9];
    const float* ab     = (const float*)d_in[10];
    const float* w_ih0  = (const float*)d_in[11];
    const float* w_hh0  = (const float*)d_in[12];
    const float* b_ih0  = (const float*)d_in[13];
    const float* b_hh0  = (const float*)d_in[14];
    const float* w_ih_r = (const float*)d_in[15];
    const float* w_hh_r = (const float*)d_in[16];
    const float* b_ih_r = (const float*)d_in[17];
    const float* b_hh_r = (const float*)d_in[18];
    const float* fcw    = (const float*)d_in[19];
    const float* fcb    = (const float*)d_in[20];

    float* out     = (float*)d_out;
    float* pred    = out;               // [B, OUT]
    float* hid_out = out + B_ * OUT_;   // [L, B, H]

    float *Wh, *energyT;
    __half *UwH, *WiH0, *WhH0, *WiHr, *WhHr, *hidH, *rnnH, *houtH;
    cudaGetSymbolAddress((void**)&Wh,      g_Wh);
    cudaGetSymbolAddress((void**)&energyT, g_energyT);
    cudaGetSymbolAddress((void**)&UwH,     g_UwH);
    cudaGetSymbolAddress((void**)&WiH0,    g_WiH0);
    cudaGetSymbolAddress((void**)&WhH0,    g_WhH0);
    cudaGetSymbolAddress((void**)&WiHr,    g_WiHr);
    cudaGetSymbolAddress((void**)&WhHr,    g_WhHr);
    cudaGetSymbolAddress((void**)&hidH,    g_hidH);
    cudaGetSymbolAddress((void**)&rnnH,    g_rnnH);
    cudaGetSymbolAddress((void**)&houtH,   g_houtH);

    cudaFuncSetAttribute(energy_async_kernel,
                         cudaFuncAttributeMaxDynamicSharedMemorySize, ESMEM_DYN);

    const float* hlast = hidden + (size_t)(L_ - 1) * B_ * H_;

    // 0) all fp32 -> fp16 conversions in one launch
    cvt_all_kernel<<<CVT_BLOCKS, 256>>>(Uw, UwH, w_ih0, WiH0, w_hh0, WhH0,
                                        w_ih_r, WiHr, w_hh_r, WhHr, hidden, hidH);

    // 1) Wh = hidden[-1] @ Ww^T + Wb
    sgemm64_kernel<<<dim3(H_ / 64, B_ / 64), 256>>>(hlast, Ww, Wb, Wh, H_, H_);

    // 2) fused energy -> energyT[b][s]
    energy_async_kernel<<<(S_ * B_) / 128, 512, ESMEM_DYN>>>(
        Es, UwH, Ub, Wh, aw, ab, energyT);

    // 3) softmax + context + embedding -> fp16 rnn (grid (2, B))
    attn_ctx_kernel<<<dim3(2, B_), 128>>>(energyT, Es, x, emb, rnnH);

    // 4) fused GRU layers
    gru_fused_kernel<768><<<dim3(H_ / 32, B_ / 64), 256>>>(
        rnnH, WiH0, hidH, WhH0, hidden, b_ih0, b_hh0, hid_out, houtH);
    for (int l = 1; l < L_; l++) {
        gru_fused_kernel<512><<<dim3(H_ / 32, B_ / 64), 256>>>(
            houtH + (size_t)(l - 1) * B_ * H_,
            WiHr + (size_t)(l - 1) * 3 * H_ * H_,
            hidH + (size_t)l * B_ * H_,
            WhHr + (size_t)(l - 1) * 3 * H_ * H_,
            hidden + (size_t)l * B_ * H_,
            b_ih_r + (size_t)(l - 1) * 3 * H_,
            b_hh_r + (size_t)(l - 1) * 3 * H_,
            hid_out + (size_t)l * B_ * H_,
            houtH + (size_t)l * B_ * H_);
    }

    // 5) predictions = h_last @ fcw^T + fcb
    sgemm64_kernel<<<dim3(OUT_ / 64, B_ / 64), 256>>>(
        hid_out + (size_t)(L_ - 1) * B_ * H_, fcw, fcb, pred, H_, OUT_);
}

// round 14
// speedup vs baseline: 1.3174x; 1.0431x over previous
#include <cuda_runtime.h>
#include <cuda_fp16.h>
#include <math.h>
#include <stdint.h>

#define S_   256
#define B_   512
#define H_   512
#define E_   256
#define L_   4
#define OUT_ 128

// ---------------- scratch (no allocs allowed) ----------------
__device__ float  g_Wh[B_ * H_];
__device__ float  g_energyT[B_ * S_];     // transposed: [b][s]
__device__ __half g_UwH[H_ * H_];
__device__ __half g_WiH0[3 * H_ * (H_ + E_)];
__device__ __half g_WhH0[3 * H_ * H_];
__device__ __half g_WiHr[(L_ - 1) * 3 * H_ * H_];
__device__ __half g_WhHr[(L_ - 1) * 3 * H_ * H_];
__device__ __half g_hidH[L_ * B_ * H_];
__device__ __half g_rnnH[B_ * (H_ + E_)];
__device__ __half g_houtH[L_ * B_ * H_];

// ---------------- helpers ----------------
__device__ __forceinline__ uint32_t smem_u32(const void* p) {
    uint32_t a;
    asm("{ .reg .u64 t; cvta.to.shared.u64 t, %1; cvt.u32.u64 %0, t; }" : "=r"(a) : "l"(p));
    return a;
}
__device__ __forceinline__ void ldsm4(uint32_t* r, uint32_t addr) {
    asm volatile("ldmatrix.sync.aligned.m8n8.x4.shared.b16 {%0,%1,%2,%3}, [%4];"
                 : "=r"(r[0]), "=r"(r[1]), "=r"(r[2]), "=r"(r[3]) : "r"(addr));
}
__device__ __forceinline__ void mma16816(float* c, const uint32_t* a, uint32_t b0, uint32_t b1) {
    asm volatile(
        "mma.sync.aligned.m16n8k16.row.col.f32.f16.f16.f32 "
        "{%0,%1,%2,%3}, {%4,%5,%6,%7}, {%8,%9}, {%0,%1,%2,%3};\n"
        : "+f"(c[0]), "+f"(c[1]), "+f"(c[2]), "+f"(c[3])
        : "r"(a[0]), "r"(a[1]), "r"(a[2]), "r"(a[3]), "r"(b0), "r"(b1));
}
__device__ __forceinline__ void cp16(uint32_t daddr, const void* saddr) {
    asm volatile("cp.async.cg.shared.global [%0], [%1], 16;" :: "r"(daddr), "l"(saddr) : "memory");
}
#define CP_COMMIT() asm volatile("cp.async.commit_group;" ::: "memory")
#define CP_WAIT(n)  asm volatile("cp.async.wait_group " #n ";" ::: "memory")

__device__ __forceinline__ void sts16(__half* dst, float4 v) {
    __half2* d = (__half2*)dst;
    d[0] = __float22half2_rn(make_float2(v.x, v.y));
    d[1] = __float22half2_rn(make_float2(v.z, v.w));
}
__device__ __forceinline__ uint32_t packh2(float a, float b) {
    __half2 h = __float22half2_rn(make_float2(a, b));
    return *reinterpret_cast<uint32_t*>(&h);
}
__device__ __forceinline__ float ftanh(float x) {
    float e = __expf(2.f * x);
    return 1.f - __fdividef(2.f, e + 1.f);
}
__device__ __forceinline__ float fsig(float x) {
    return __fdividef(1.f, 1.f + __expf(-x));
}

// ---------------- merged fp32 -> fp16 conversions (one launch) ----------------
#define Q_UW   (H_ * H_ / 4)
#define Q_WI0  (Q_UW + 3 * H_ * (H_ + E_) / 4)
#define Q_WH0  (Q_WI0 + 3 * H_ * H_ / 4)
#define Q_WIR  (Q_WH0 + (L_ - 1) * 3 * H_ * H_ / 4)
#define Q_WHR  (Q_WIR + (L_ - 1) * 3 * H_ * H_ / 4)
#define Q_HID  (Q_WHR + L_ * B_ * H_ / 4)
#define CVT_BLOCKS (Q_HID / 256)

__global__ void cvt_all_kernel(
    const float* __restrict__ Uw,   __half* __restrict__ UwH,
    const float* __restrict__ wi0,  __half* __restrict__ WiH0,
    const float* __restrict__ wh0,  __half* __restrict__ WhH0,
    const float* __restrict__ wir,  __half* __restrict__ WiHr,
    const float* __restrict__ whr,  __half* __restrict__ WhHr,
    const float* __restrict__ hid,  __half* __restrict__ hidH) {
    const int i = blockIdx.x * 256 + threadIdx.x;
    const float* src;
    __half* dst;
    int off;
    if (i < Q_UW)       { src = Uw;  dst = UwH;  off = 0; }
    else if (i < Q_WI0) { src = wi0; dst = WiH0; off = Q_UW; }
    else if (i < Q_WH0) { src = wh0; dst = WhH0; off = Q_WI0; }
    else if (i < Q_WIR) { src = wir; dst = WiHr; off = Q_WH0; }
    else if (i < Q_WHR) { src = whr; dst = WhHr; off = Q_WIR; }
    else                { src = hid; dst = hidH; off = Q_WHR; }
    const int j = i - off;
    float4 v = ((const float4*)src)[j];
    uint2 o;
    o.x = packh2(v.x, v.y);
    o.y = packh2(v.z, v.w);
    ((uint2*)dst)[j] = o;
}

// ============================================================
// Energy kernel: 32-k iterations, 3-stage cp.async (from R13).
// ============================================================
#define EASZ 20480                  // A: 128 rows * 160B
#define EWSZ 20480                  // W: 256 rows * 80B
#define ESTG (EASZ + EWSZ)
#define ESMEM_DYN (512 + 3 * ESTG)

__global__ void __launch_bounds__(512, 1) energy_async_kernel(
    const float* __restrict__ Es, const __half* __restrict__ UwH,
    const float* __restrict__ Ub, const float* __restrict__ Wh,
    const float* __restrict__ aw, const float* __restrict__ ab,
    float* __restrict__ energyT) {
    extern __shared__ __align__(16) char dsm[];
    float* esum = (float*)dsm;
    char* tiles = dsm + 512;
    const uint32_t tBase = smem_u32(tiles);

    const int tid = threadIdx.x;
    const int lane = tid & 31, wid = tid >> 5;
    const int wm = wid >> 3, wn = wid & 7;
    const int g = lane >> 2, tg = lane & 3;
    const int lr = (lane & 7) + ((lane >> 3) & 1) * 8;
    const int lb = ((lane >> 4) & 1) * 16;
    const int r0 = blockIdx.x * 128;
    const int b0 = r0 & (B_ - 1);

    const int aRow0 = tid >> 3, aQ0 = tid & 7;
    const int aRow1 = (tid + 512) >> 3, aQ1 = (tid + 512) & 7;
    const int wRow0 = tid >> 1 >> 1, wQ0 = tid & 3;   // tid>>2
    const int wRow1 = (tid + 512) >> 2, wQ1 = (tid + 512) & 3;

    if (tid < 128) esum[tid] = 0.f;
    __syncthreads();

    for (int nc = 0; nc < 2; nc++) {
        const float* Abase = Es + (size_t)r0 * H_;
        const __half* Wb2 = UwH + (size_t)(nc * 256) * H_;
        float acc[4][4][4] = {};

#pragma unroll
        for (int s = 0; s < 2; s++) {
            const uint32_t sb = tBase + (uint32_t)s * ESTG;
            cp16(sb + aRow0 * 160 + aQ0 * 16, Abase + (size_t)aRow0 * H_ + s * 32 + aQ0 * 4);
            cp16(sb + aRow1 * 160 + aQ1 * 16, Abase + (size_t)aRow1 * H_ + s * 32 + aQ1 * 4);
            cp16(sb + EASZ + wRow0 * 80 + wQ0 * 16, Wb2 + (size_t)wRow0 * H_ + s * 32 + wQ0 * 8);
            cp16(sb + EASZ + wRow1 * 80 + wQ1 * 16, Wb2 + (size_t)wRow1 * H_ + s * 32 + wQ1 * 8);
            CP_COMMIT();
        }

        for (int it = 0; it < 16; it++) {
            const int s = it % 3;
            CP_WAIT(1);
            __syncthreads();

            const float* sA = (const float*)(tiles + s * ESTG);
            const uint32_t wOff = tBase + (uint32_t)s * ESTG + EASZ;

#pragma unroll
            for (int ks = 0; ks < 2; ks++) {
                uint32_t af[4][4];
#pragma unroll
                for (int mi = 0; mi < 4; mi++) {
                    const int rb = wm * 64 + mi * 16 + g;
                    const int cb = ks * 16 + tg * 2;
                    float2 f0 = *(const float2*)&sA[rb * 40 + cb];
                    float2 f1 = *(const float2*)&sA[(rb + 8) * 40 + cb];
                    float2 f2 = *(const float2*)&sA[rb * 40 + cb + 8];
                    float2 f3 = *(const float2*)&sA[(rb + 8) * 40 + cb + 8];
                    af[mi][0] = packh2(f0.x, f0.y);
                    af[mi][1] = packh2(f1.x, f1.y);
                    af[mi][2] = packh2(f2.x, f2.y);
                    af[mi][3] = packh2(f3.x, f3.y);
                }
                uint32_t bt[2][4];
#pragma unroll
                for (int nt = 0; nt < 2; nt++)
                    ldsm4(bt[nt], wOff + (uint32_t)(wn * 32 + nt * 16 + lr) * 80 + ks * 32 + lb);
#pragma unroll
                for (int mi = 0; mi < 4; mi++)
#pragma unroll
                    for (int ni = 0; ni < 4; ni++) {
                        const int nt = ni >> 1, sub = ni & 1;
                        mma16816(acc[mi][ni], af[mi], bt[nt][sub ? 1 : 0], bt[nt][sub ? 3 : 2]);
                    }
            }
            if (it + 2 < 16) {
                const int ns = (it + 2) % 3;
                const uint32_t sb = tBase + (uint32_t)ns * ESTG;
                cp16(sb + aRow0 * 160 + aQ0 * 16, Abase + (size_t)aRow0 * H_ + (it + 2) * 32 + aQ0 * 4);
                cp16(sb + aRow1 * 160 + aQ1 * 16, Abase + (size_t)aRow1 * H_ + (it + 2) * 32 + aQ1 * 4);
                cp16(sb + EASZ + wRow0 * 80 + wQ0 * 16, Wb2 + (size_t)wRow0 * H_ + (it + 2) * 32 + wQ0 * 8);
                cp16(sb + EASZ + wRow1 * 80 + wQ1 * 16, Wb2 + (size_t)wRow1 * H_ + (it + 2) * 32 + wQ1 * 8);
            }
            CP_COMMIT();
        }

#pragma unroll
        for (int mi = 0; mi < 4; mi++)
#pragma unroll
            for (int hf = 0; hf < 2; hf++) {
                const int rl = wm * 64 + mi * 16 + g + hf * 8;
                const float* WhR = Wh + (size_t)(b0 + rl) * H_;
                float s = 0.f;
#pragma unroll
                for (int ni = 0; ni < 4; ni++) {
                    const int col = nc * 256 + wn * 32 + ni * 8 + tg * 2;
                    float v0 = acc[mi][ni][hf * 2 + 0] + Ub[col] + WhR[col];
                    float v1 = acc[mi][ni][hf * 2 + 1] + Ub[col + 1] + WhR[col + 1];
                    s += ftanh(v0) * aw[col] + ftanh(v1) * aw[col + 1];
                }
                s += __shfl_xor_sync(0xffffffffu, s, 1);
                s += __shfl_xor_sync(0xffffffffu, s, 2);
                if (tg == 0) atomicAdd(&esum[rl], s);
            }
        __syncthreads();   // stage 0 re-written by next nc's prologue
    }
    if (tid < 128) {
        const int r = r0 + tid;
        energyT[(size_t)(r & (B_ - 1)) * S_ + (r >> 9)] = esum[tid] + ab[0];
    }
}

// ============================================================
// GRU fused layer: 32-k chunks, 3-stage cp.async pipeline.
// 256 thr, tile 64 rows x 32 h-cols. smem rows/stage (80B each):
// 0-63 Ai | 64-127 Ah | 128-223 Wi | 224-319 Wh. Dynamic smem.
// ============================================================
#define GSTG (320 * 80)             // 25600 per stage
#define GSMEM_DYN (3 * GSTG)        // 76800

template<int KI>
__global__ void __launch_bounds__(256, 1) gru_fused_kernel(
    const __half* __restrict__ AiH, const __half* __restrict__ WiH,
    const __half* __restrict__ AhH, const __half* __restrict__ WhH,
    const float* __restrict__ Ahf,
    const float* __restrict__ bi, const float* __restrict__ bh,
    float* __restrict__ hout, __half* __restrict__ houtH) {
    extern __shared__ __align__(16) char sm[];

    const int tid = threadIdx.x;
    const int lane = tid & 31, wid = tid >> 5;
    const int wm = wid >> 1, wn = wid & 1;
    const int gl = lane >> 2, tg = lane & 3;
    const int lr = (lane & 7) + ((lane >> 3) & 1) * 8;
    const int lb = ((lane >> 4) & 1) * 16;
    const int m0 = blockIdx.y * 64;
    const int nb = blockIdx.x * 32;
    const uint32_t base = smem_u32(sm);

    // fill descriptors: 1280 cp16 ops (320 rows x 4 quads), 5 per thread
    const __half* srcp[5];
    uint32_t dsto[5];
    bool ish[5];
#pragma unroll
    for (int i = 0; i < 5; i++) {
        const int idx = i * 256 + tid;
        const int row = idx >> 2, quad = idx & 3;
        const __half* p;
        bool h;
        if (row < 64)       { p = AiH + (size_t)(m0 + row) * KI; h = false; }
        else if (row < 128) { p = AhH + (size_t)(m0 + row - 64) * H_; h = true; }
        else if (row < 224) { const int q = row - 128; p = WiH + (size_t)((q >> 5) * H_ + nb + (q & 31)) * KI; h = false; }
        else                { const int q = row - 224; p = WhH + (size_t)((q >> 5) * H_ + nb + (q & 31)) * H_; h = true; }
        srcp[i] = p + quad * 8;
        dsto[i] = row * 80 + quad * 16;
        ish[i] = h;
    }

    float acc_rz[2][2][4] = {};
    float acc_n0[2][4] = {};
    float acc_n1[2][4] = {};

    constexpr int NIT = KI / 32;    // 24 (layer0) or 16
    constexpr int NHIT = H_ / 32;   // 16: iterations with h-side active

    // prologue stages 0,1
#pragma unroll
    for (int s = 0; s < 2; s++) {
#pragma unroll
        for (int i = 0; i < 5; i++)
            if (!ish[i] || s < NHIT)
                cp16(base + s * GSTG + dsto[i], srcp[i] + s * 32);
        CP_COMMIT();
    }

    for (int it = 0; it < NIT; it++) {
        const int s = it % 3;
        CP_WAIT(1);
        __syncthreads();

        const uint32_t off = base + (uint32_t)s * GSTG;
        const bool act_h = (it < NHIT);
#pragma unroll
        for (int ks = 0; ks < 2; ks++) {
            const uint32_t lbk = (uint32_t)(ks * 32 + lb);
            uint32_t afi[4], afh[4], bwi[3][4], bwh[3][4];
            ldsm4(afi, off + (uint32_t)(wm * 16 + lr) * 80 + lbk);
#pragma unroll
            for (int gt = 0; gt < 3; gt++)
                ldsm4(bwi[gt], off + (uint32_t)(128 + gt * 32 + wn * 16 + lr) * 80 + lbk);
            if (act_h) {
                ldsm4(afh, off + (uint32_t)(64 + wm * 16 + lr) * 80 + lbk);
#pragma unroll
                for (int gt = 0; gt < 3; gt++)
                    ldsm4(bwh[gt], off + (uint32_t)(224 + gt * 32 + wn * 16 + lr) * 80 + lbk);
            }
#pragma unroll
            for (int sub = 0; sub < 2; sub++) {
                mma16816(acc_rz[0][sub], afi, bwi[0][sub], bwi[0][sub + 2]);
                mma16816(acc_rz[1][sub], afi, bwi[1][sub], bwi[1][sub + 2]);
                mma16816(acc_n0[sub],    afi, bwi[2][sub], bwi[2][sub + 2]);
            }
            if (act_h) {
#pragma unroll
                for (int sub = 0; sub < 2; sub++) {
                    mma16816(acc_rz[0][sub], afh, bwh[0][sub], bwh[0][sub + 2]);
                    mma16816(acc_rz[1][sub], afh, bwh[1][sub], bwh[1][sub + 2]);
                    mma16816(acc_n1[sub],    afh, bwh[2][sub], bwh[2][sub + 2]);
                }
            }
        }
        if (it + 2 < NIT) {
            const int ns = (it + 2) % 3;
#pragma unroll
            for (int i = 0; i < 5; i++)
                if (!ish[i] || (it + 2) < NHIT)
                    cp16(base + ns * GSTG + dsto[i], srcp[i] + (it + 2) * 32);
        }
        CP_COMMIT();
    }

    // epilogue: gate nonlinearity, h update
#pragma unroll
    for (int hf = 0; hf < 2; hf++) {
        const int row = m0 + wm * 16 + gl + hf * 8;
#pragma unroll
        for (int sub = 0; sub < 2; sub++) {
            const int col = nb + wn * 16 + sub * 8 + tg * 2;
            float2 hp = *(const float2*)&Ahf[(size_t)row * H_ + col];
            float2 o;
#pragma unroll
            for (int j = 0; j < 2; j++) {
                const int cj = col + j;
                float rr = fsig(acc_rz[0][sub][hf * 2 + j] + bi[cj] + bh[cj]);
                float zz = fsig(acc_rz[1][sub][hf * 2 + j] + bi[H_ + cj] + bh[H_ + cj]);
                float nn = ftanh(acc_n0[sub][hf * 2 + j] + bi[2 * H_ + cj] +
                                 rr * (acc_n1[sub][hf * 2 + j] + bh[2 * H_ + cj]));
                float hv = j ? hp.y : hp.x;
                float res = fmaf(zz, hv - nn, nn);
                if (j) o.y = res; else o.x = res;
            }
            *(float2*)&hout[(size_t)row * H_ + col] = o;
            *(__half2*)&houtH[(size_t)row * H_ + col] = __float22half2_rn(o);
        }
    }
}

// ---------------- small GEMM: C[M,N] = A@W^T + bias (fp32 in, 64x64) ----------------
__global__ void __launch_bounds__(256, 2) sgemm64_kernel(
    const float* __restrict__ A, const float* __restrict__ W,
    const float* __restrict__ bias, float* __restrict__ C, int K, int N) {
    __shared__ __align__(16) __half sm[2 * 128 * 24];

    const int tid = threadIdx.x;
    const int lane = tid & 31, wid = tid >> 5;
    const int wm = wid >> 1, wn = wid & 1;
    const int g = lane >> 2, tg = lane & 3;
    const int lr = (lane & 7) + ((lane >> 3) & 1) * 8;
    const int lb = ((lane >> 4) & 1) * 16;
    const int m0 = blockIdx.y * 64, n0 = blockIdx.x * 64;
    const uint32_t base = smem_u32(sm);

    const int r = tid >> 2, c = (tid & 3) * 4;
    float acc[4][4] = {};
    float4 ra, rw;
    ra = *(const float4*)&A[(size_t)(m0 + r) * K + c];
    rw = *(const float4*)&W[(size_t)(n0 + r) * K + c];
    sts16(sm + r * 24 + c, ra);
    sts16(sm + (64 + r) * 24 + c, rw);
    __syncthreads();

    const int nk = K / 16;
    for (int kt = 0; kt < nk; kt++) {
        const int p = kt & 1;
        if (kt + 1 < nk) {
            ra = *(const float4*)&A[(size_t)(m0 + r) * K + (kt + 1) * 16 + c];
            rw = *(const float4*)&W[(size_t)(n0 + r) * K + (kt + 1) * 16 + c];
        }
        const uint32_t off = base + (uint32_t)p * 128 * 48;
        uint32_t af[4], bt[2][4];
        ldsm4(af, off + (uint32_t)(wm * 16 + lr) * 48 + lb);
#pragma unroll
        for (int nt = 0; nt < 2; nt++)
            ldsm4(bt[nt], off + (uint32_t)(64 + wn * 32 + nt * 16 + lr) * 48 + lb);
#pragma unroll
        for (int ni = 0; ni < 4; ni++) {
            const int nt = ni >> 1, sub = ni & 1;
            mma16816(acc[ni], af, bt[nt][sub ? 1 : 0], bt[nt][sub ? 3 : 2]);
        }
        if (kt + 1 < nk) {
            __half* d = sm + (p ^ 1) * 128 * 24;
            sts16(d + r * 24 + c, ra);
            sts16(d + (64 + r) * 24 + c, rw);
        }
        __syncthreads();
    }

#pragma unroll
    for (int hf = 0; hf < 2; hf++) {
        const int row = m0 + wm * 16 + g + hf * 8;
#pragma unroll
        for (int ni = 0; ni < 4; ni++) {
            const int col = n0 + wn * 32 + ni * 8 + tg * 2;
            float2 o;
            o.x = acc[ni][hf * 2 + 0] + bias[col];
            o.y = acc[ni][hf * 2 + 1] + bias[col + 1];
            *(float2*)&C[(size_t)row * N + col] = o;
        }
    }
}

// ============================================================
// attn+context+emb: grid (4, B), 128 threads (R11 geometry).
// ============================================================
__global__ void __launch_bounds__(128) attn_ctx_kernel(
    const float* __restrict__ energyT, const float* __restrict__ Es,
    const int* __restrict__ x, const float* __restrict__ emb,
    __half* __restrict__ rnnH) {
    __shared__ float sv[S_];
    __shared__ float att[S_];
    const int q = blockIdx.x;
    const int b = blockIdx.y;
    const int t = threadIdx.x;

    float e0 = energyT[(size_t)b * S_ + t];
    float e1 = energyT[(size_t)b * S_ + 128 + t];
    sv[t] = fmaxf(e0, e1);
    __syncthreads();
    for (int off = 64; off; off >>= 1) {
        if (t < off) sv[t] = fmaxf(sv[t], sv[t + off]);
        __syncthreads();
    }
    const float m = sv[0];
    __syncthreads();
    float x0 = __expf(e0 - m), x1 = __expf(e1 - m);
    att[t] = x0;
    att[t + 128] = x1;
    sv[t] = x0 + x1;
    __syncthreads();
    for (int off = 64; off; off >>= 1) {
        if (t < off) sv[t] += sv[t + off];
        __syncthreads();
    }
    const float inv = __fdividef(1.f, sv[0]);
    __syncthreads();

    // context: h = q*128 + t (one float per thread)
    const int h = q * 128 + t;
    const float* base = Es + (size_t)b * H_ + h;
    float a0 = 0.f, a1 = 0.f, a2 = 0.f, a3 = 0.f;
#pragma unroll 2
    for (int s = 0; s < S_; s += 4) {
        a0 = fmaf(att[s + 0], base[(size_t)(s + 0) * B_ * H_], a0);
        a1 = fmaf(att[s + 1], base[(size_t)(s + 1) * B_ * H_], a1);
        a2 = fmaf(att[s + 2], base[(size_t)(s + 2) * B_ * H_], a2);
        a3 = fmaf(att[s + 3], base[(size_t)(s + 3) * B_ * H_], a3);
    }
    rnnH[(size_t)b * (H_ + E_) + h] = __float2half(((a0 + a1) + (a2 + a3)) * inv);

    // embedding: 4 blocks x 64 lanes cover E_=256
    if (t < 64) {
        const int col = q * 64 + t;
        rnnH[(size_t)b * (H_ + E_) + H_ + col] = __float2half(emb[(size_t)x[b] * E_ + col]);
    }
}

// ---------------- launch ----------------
extern "C" void kernel_launch(void* const* d_in, const int* in_sizes, int n_in,
                              void* d_out, int out_size) {
    const int*   x      = (const int*)  d_in[0];
    const float* Es     = (const float*)d_in[1];
    const float* hidden = (const float*)d_in[2];
    const float* emb    = (const float*)d_in[4];
    const float* Uw     = (const float*)d_in[5];
    const float* Ub     = (const float*)d_in[6];
    const float* Ww     = (const float*)d_in[7];
    const float* Wb     = (const float*)d_in[8];
    const float* aw     = (const float*)d_in[9];
    const float* ab     = (const float*)d_in[10];
    const float* w_ih0  = (const float*)d_in[11];
    const float* w_hh0  = (const float*)d_in[12];
    const float* b_ih0  = (const float*)d_in[13];
    const float* b_hh0  = (const float*)d_in[14];
    const float* w_ih_r = (const float*)d_in[15];
    const float* w_hh_r = (const float*)d_in[16];
    const float* b_ih_r = (const float*)d_in[17];
    const float* b_hh_r = (const float*)d_in[18];
    const float* fcw    = (const float*)d_in[19];
    const float* fcb    = (const float*)d_in[20];

    float* out     = (float*)d_out;
    float* pred    = out;               // [B, OUT]
    float* hid_out = out + B_ * OUT_;   // [L, B, H]

    float *Wh, *energyT;
    __half *UwH, *WiH0, *WhH0, *WiHr, *WhHr, *hidH, *rnnH, *houtH;
    cudaGetSymbolAddress((void**)&Wh,      g_Wh);
    cudaGetSymbolAddress((void**)&energyT, g_energyT);
    cudaGetSymbolAddress((void**)&UwH,     g_UwH);
    cudaGetSymbolAddress((void**)&WiH0,    g_WiH0);
    cudaGetSymbolAddress((void**)&WhH0,    g_WhH0);
    cudaGetSymbolAddress((void**)&WiHr,    g_WiHr);
    cudaGetSymbolAddress((void**)&WhHr,    g_WhHr);
    cudaGetSymbolAddress((void**)&hidH,    g_hidH);
    cudaGetSymbolAddress((void**)&rnnH,    g_rnnH);
    cudaGetSymbolAddress((void**)&houtH,   g_houtH);

    cudaFuncSetAttribute(energy_async_kernel,
                         cudaFuncAttributeMaxDynamicSharedMemorySize, ESMEM_DYN);
    cudaFuncSetAttribute(gru_fused_kernel<768>,
                         cudaFuncAttributeMaxDynamicSharedMemorySize, GSMEM_DYN);
    cudaFuncSetAttribute(gru_fused_kernel<512>,
                         cudaFuncAttributeMaxDynamicSharedMemorySize, GSMEM_DYN);

    const float* hlast = hidden + (size_t)(L_ - 1) * B_ * H_;

    // 0) all fp32 -> fp16 conversions in one launch
    cvt_all_kernel<<<CVT_BLOCKS, 256>>>(Uw, UwH, w_ih0, WiH0, w_hh0, WhH0,
                                        w_ih_r, WiHr, w_hh_r, WhHr, hidden, hidH);

    // 1) Wh = hidden[-1] @ Ww^T + Wb
    sgemm64_kernel<<<dim3(H_ / 64, B_ / 64), 256>>>(hlast, Ww, Wb, Wh, H_, H_);

    // 2) fused energy -> energyT[b][s]
    energy_async_kernel<<<(S_ * B_) / 128, 512, ESMEM_DYN>>>(
        Es, UwH, Ub, Wh, aw, ab, energyT);

    // 3) softmax + context + embedding -> fp16 rnn (grid (4, B))
    attn_ctx_kernel<<<dim3(4, B_), 128>>>(energyT, Es, x, emb, rnnH);

    // 4) fused GRU layers (32-k chunk, 3-stage cp.async)
    gru_fused_kernel<768><<<dim3(H_ / 32, B_ / 64), 256, GSMEM_DYN>>>(
        rnnH, WiH0, hidH, WhH0, hidden, b_ih0, b_hh0, hid_out, houtH);
    for (int l = 1; l < L_; l++) {
        gru_fused_kernel<512><<<dim3(H_ / 32, B_ / 64), 256, GSMEM_DYN>>>(
            houtH + (size_t)(l - 1) * B_ * H_,
            WiHr + (size_t)(l - 1) * 3 * H_ * H_,
            hidH + (size_t)l * B_ * H_,
            WhHr + (size_t)(l - 1) * 3 * H_ * H_,
            hidden + (size_t)l * B_ * H_,
            b_ih_r + (size_t)(l - 1) * 3 * H_,
            b_hh_r + (size_t)(l - 1) * 3 * H_,
            hid_out + (size_t)l * B_ * H_,
            houtH + (size_t)l * B_ * H_);
    }

    // 5) predictions = h_last @ fcw^T + fcb
    sgemm64_kernel<<<dim3(OUT_ / 64, B_ / 64), 256>>>(
        hid_out + (size_t)(L_ - 1) * B_ * H_, fcw, fcb, pred, H_, OUT_);
}